// round 1
// baseline (speedup 1.0000x reference)
#include <cuda_runtime.h>

#define NB 4
#define NH 4
#define DH 64
#define ND 2048
#define QD 512
#define INNER 256

// Scratch (allocation-free: __device__ globals)
__device__ float g_Q [NB*NH*ND*DH];
__device__ float g_Q2[NB*NH*ND*DH];
__device__ float g_K [NB*NH*ND*DH];
__device__ float g_V [NB*NH*ND*DH];
__device__ float g_Ao[NB*ND*INNER];

// ---------------------------------------------------------------------------
// Projection GEMM: C = A[8192,512] @ W[512,256], written head-split [b,h,n,64]
// blockIdx.z selects which of the 4 projections.
// ---------------------------------------------------------------------------
__global__ __launch_bounds__(256) void proj_kernel(
    const float* __restrict__ x1, const float* __restrict__ x2,
    const float* __restrict__ ctx,
    const float* __restrict__ Wq, const float* __restrict__ Wq2,
    const float* __restrict__ Wk, const float* __restrict__ Wv)
{
    __shared__ float As[16][65];
    __shared__ float Bs[16][64];

    const float* A; const float* Bw; float* C;
    int which = blockIdx.z;
    if      (which == 0) { A = x1;  Bw = Wq;  C = g_Q;  }
    else if (which == 1) { A = x2;  Bw = Wq2; C = g_Q2; }
    else if (which == 2) { A = ctx; Bw = Wk;  C = g_K;  }
    else                 { A = ctx; Bw = Wv;  C = g_V;  }

    int tid  = threadIdx.x;
    int row0 = blockIdx.x * 64;
    int col0 = blockIdx.y * 64;      // multiple of 64 -> one head per block
    int tyr  = (tid >> 4) << 2;      // 0..60
    int txc  = (tid & 15) << 2;      // 0..60

    int lr = tid >> 2;               // A-load row 0..63
    int lk = (tid & 3) << 2;         // A-load k 0,4,8,12
    int bk = tid >> 4;               // B-load k 0..15
    int bc = (tid & 15) << 2;        // B-load col

    float acc[4][4] = {};

    for (int k0 = 0; k0 < QD; k0 += 16) {
        float4 av = *(const float4*)&A[(size_t)(row0 + lr) * QD + k0 + lk];
        As[lk + 0][lr] = av.x; As[lk + 1][lr] = av.y;
        As[lk + 2][lr] = av.z; As[lk + 3][lr] = av.w;
        *(float4*)&Bs[bk][bc] = *(const float4*)&Bw[(size_t)(k0 + bk) * INNER + col0 + bc];
        __syncthreads();
        #pragma unroll
        for (int k = 0; k < 16; k++) {
            float4 bv = *(float4*)&Bs[k][txc];
            float a0 = As[k][tyr], a1 = As[k][tyr + 1];
            float a2 = As[k][tyr + 2], a3 = As[k][tyr + 3];
            acc[0][0] += a0 * bv.x; acc[0][1] += a0 * bv.y; acc[0][2] += a0 * bv.z; acc[0][3] += a0 * bv.w;
            acc[1][0] += a1 * bv.x; acc[1][1] += a1 * bv.y; acc[1][2] += a1 * bv.z; acc[1][3] += a1 * bv.w;
            acc[2][0] += a2 * bv.x; acc[2][1] += a2 * bv.y; acc[2][2] += a2 * bv.z; acc[2][3] += a2 * bv.w;
            acc[3][0] += a3 * bv.x; acc[3][1] += a3 * bv.y; acc[3][2] += a3 * bv.z; acc[3][3] += a3 * bv.w;
        }
        __syncthreads();
    }

    int h = col0 >> 6;               // head index
    #pragma unroll
    for (int i = 0; i < 4; i++) {
        int R  = row0 + tyr + i;
        int b  = R >> 11;
        int ni = R & 2047;
        float4 o = make_float4(acc[i][0], acc[i][1], acc[i][2], acc[i][3]);
        *(float4*)&C[(((size_t)(b * NH + h)) * ND + ni) * DH + txc] = o;
    }
}

// ---------------------------------------------------------------------------
// Dual-softmax flash attention. One CTA: (b,h) x 64-query tile. 256 threads.
// ---------------------------------------------------------------------------
#define SP 68   // smem pitch (floats): float4-aligned, breaks worst conflicts

__global__ __launch_bounds__(256) void attn_kernel()
{
    extern __shared__ float sm[];
    float* Qs  = sm;
    float* Q2s = Qs  + 64 * SP;
    float* Ks  = Q2s + 64 * SP;
    float* Vs  = Ks  + 64 * SP;
    float* S1  = Vs  + 64 * SP;
    float* S2  = S1  + 64 * SP;
    float* m1  = S2  + 64 * SP;
    float* l1  = m1 + 64;
    float* m2  = l1 + 64;
    float* l2  = m2 + 64;
    float* a1s = l2 + 64;
    float* a2s = a1s + 64;

    int tid = threadIdx.x;
    int bh  = blockIdx.y;
    int i0  = blockIdx.x * 64;
    const float* Qb  = g_Q  + (size_t)bh * ND * DH;
    const float* Q2b = g_Q2 + (size_t)bh * ND * DH;
    const float* Kb  = g_K  + (size_t)bh * ND * DH;
    const float* Vb  = g_V  + (size_t)bh * ND * DH;

    // Load Q / Q2 tiles (64 x 64)
    for (int idx = tid; idx < 64 * 16; idx += 256) {
        int r = idx >> 4, c4 = (idx & 15) << 2;
        *(float4*)&Qs [r * SP + c4] = *(const float4*)&Qb [(size_t)(i0 + r) * DH + c4];
        *(float4*)&Q2s[r * SP + c4] = *(const float4*)&Q2b[(size_t)(i0 + r) * DH + c4];
    }
    if (tid < 64) { m1[tid] = -1e30f; l1[tid] = 0.f; m2[tid] = -1e30f; l2[tid] = 0.f; }

    int tyr = (tid >> 4) << 2;
    int txc = (tid & 15) << 2;
    float O1[4][4] = {}, O2[4][4] = {};
    const float scale = 0.125f;      // 64^-0.5

    for (int kt = 0; kt < 32; kt++) {
        int k0 = kt * 64;
        // Load K / V tiles
        for (int idx = tid; idx < 64 * 16; idx += 256) {
            int r = idx >> 4, c4 = (idx & 15) << 2;
            *(float4*)&Ks[r * SP + c4] = *(const float4*)&Kb[(size_t)(k0 + r) * DH + c4];
            *(float4*)&Vs[r * SP + c4] = *(const float4*)&Vb[(size_t)(k0 + r) * DH + c4];
        }
        __syncthreads();

        // ---- S = Q K^T, S2 = Q2 K^T (64x64 tile, 4x4 per thread) ----
        float acc1[4][4] = {}, acc2[4][4] = {};
        #pragma unroll
        for (int dd = 0; dd < 64; dd += 4) {
            float kvv[4][4], qvv[4][4], q2v[4][4];
            #pragma unroll
            for (int j = 0; j < 4; j++) {
                float4 t = *(float4*)&Ks[(txc + j) * SP + dd];
                kvv[j][0] = t.x; kvv[j][1] = t.y; kvv[j][2] = t.z; kvv[j][3] = t.w;
            }
            #pragma unroll
            for (int i = 0; i < 4; i++) {
                float4 t  = *(float4*)&Qs [(tyr + i) * SP + dd];
                qvv[i][0] = t.x; qvv[i][1] = t.y; qvv[i][2] = t.z; qvv[i][3] = t.w;
                float4 u  = *(float4*)&Q2s[(tyr + i) * SP + dd];
                q2v[i][0] = u.x; q2v[i][1] = u.y; q2v[i][2] = u.z; q2v[i][3] = u.w;
            }
            #pragma unroll
            for (int i = 0; i < 4; i++)
                #pragma unroll
                for (int j = 0; j < 4; j++) {
                    #pragma unroll
                    for (int c = 0; c < 4; c++) {
                        acc1[i][j] += qvv[i][c] * kvv[j][c];
                        acc2[i][j] += q2v[i][c] * kvv[j][c];
                    }
                }
        }
        #pragma unroll
        for (int i = 0; i < 4; i++) {
            float4 s1 = make_float4(acc1[i][0] * scale, acc1[i][1] * scale,
                                    acc1[i][2] * scale, acc1[i][3] * scale);
            float4 s2 = make_float4(acc2[i][0] * scale, acc2[i][1] * scale,
                                    acc2[i][2] * scale, acc2[i][3] * scale);
            *(float4*)&S1[(tyr + i) * SP + txc] = s1;
            *(float4*)&S2[(tyr + i) * SP + txc] = s2;
        }
        __syncthreads();

        // ---- online softmax: 4 threads per row, 16 cols each ----
        {
            int row = tid >> 2, base = (tid & 3) << 4;
            // S1
            float* Sr = S1 + row * SP + base;
            float mx = -1e30f;
            #pragma unroll
            for (int c = 0; c < 16; c++) mx = fmaxf(mx, Sr[c]);
            mx = fmaxf(mx, __shfl_xor_sync(0xffffffffu, mx, 1));
            mx = fmaxf(mx, __shfl_xor_sync(0xffffffffu, mx, 2));
            float mo = m1[row], mn = fmaxf(mo, mx);
            float s = 0.f;
            #pragma unroll
            for (int c = 0; c < 16; c++) { float p = __expf(Sr[c] - mn); Sr[c] = p; s += p; }
            s += __shfl_xor_sync(0xffffffffu, s, 1);
            s += __shfl_xor_sync(0xffffffffu, s, 2);
            if ((tid & 3) == 0) {
                float al = __expf(mo - mn);
                l1[row] = l1[row] * al + s; m1[row] = mn; a1s[row] = al;
            }
            // S2
            Sr = S2 + row * SP + base;
            mx = -1e30f;
            #pragma unroll
            for (int c = 0; c < 16; c++) mx = fmaxf(mx, Sr[c]);
            mx = fmaxf(mx, __shfl_xor_sync(0xffffffffu, mx, 1));
            mx = fmaxf(mx, __shfl_xor_sync(0xffffffffu, mx, 2));
            mo = m2[row]; mn = fmaxf(mo, mx);
            s = 0.f;
            #pragma unroll
            for (int c = 0; c < 16; c++) { float p = __expf(Sr[c] - mn); Sr[c] = p; s += p; }
            s += __shfl_xor_sync(0xffffffffu, s, 1);
            s += __shfl_xor_sync(0xffffffffu, s, 2);
            if ((tid & 3) == 0) {
                float al = __expf(mo - mn);
                l2[row] = l2[row] * al + s; m2[row] = mn; a2s[row] = al;
            }
        }
        __syncthreads();

        // ---- O += P V (rescale first) ----
        #pragma unroll
        for (int i = 0; i < 4; i++) {
            float a1 = a1s[tyr + i], a2 = a2s[tyr + i];
            #pragma unroll
            for (int j = 0; j < 4; j++) { O1[i][j] *= a1; O2[i][j] *= a2; }
        }
        #pragma unroll
        for (int kk = 0; kk < 64; kk += 4) {
            float vvv[4][4], p1[4][4], p2[4][4];
            #pragma unroll
            for (int t = 0; t < 4; t++) {
                float4 v = *(float4*)&Vs[(kk + t) * SP + txc];
                vvv[t][0] = v.x; vvv[t][1] = v.y; vvv[t][2] = v.z; vvv[t][3] = v.w;
            }
            #pragma unroll
            for (int i = 0; i < 4; i++) {
                float4 a = *(float4*)&S1[(tyr + i) * SP + kk];
                p1[i][0] = a.x; p1[i][1] = a.y; p1[i][2] = a.z; p1[i][3] = a.w;
                float4 b = *(float4*)&S2[(tyr + i) * SP + kk];
                p2[i][0] = b.x; p2[i][1] = b.y; p2[i][2] = b.z; p2[i][3] = b.w;
            }
            #pragma unroll
            for (int i = 0; i < 4; i++)
                #pragma unroll
                for (int j = 0; j < 4; j++) {
                    #pragma unroll
                    for (int t = 0; t < 4; t++) {
                        O1[i][j] += p1[i][t] * vvv[t][j];
                        O2[i][j] += p2[i][t] * vvv[t][j];
                    }
                }
        }
        __syncthreads();
    }

    // epilogue: out = 0.3*O1/l1 + 0.7*O2/l2, recombined [b, n, h*64+d]
    int b = bh >> 2, h = bh & 3;
    #pragma unroll
    for (int i = 0; i < 4; i++) {
        float inv1 = 0.3f / l1[tyr + i];
        float inv2 = 0.7f / l2[tyr + i];
        float4 o;
        o.x = O1[i][0] * inv1 + O2[i][0] * inv2;
        o.y = O1[i][1] * inv1 + O2[i][1] * inv2;
        o.z = O1[i][2] * inv1 + O2[i][2] * inv2;
        o.w = O1[i][3] * inv1 + O2[i][3] * inv2;
        *(float4*)&g_Ao[((size_t)b * ND + i0 + tyr + i) * INNER + h * DH + txc] = o;
    }
}

// ---------------------------------------------------------------------------
// Output projection: out = Ao[8192,256] @ Wo[256,512] + bo
// ---------------------------------------------------------------------------
__global__ __launch_bounds__(256) void out_proj_kernel(
    const float* __restrict__ Wo, const float* __restrict__ bo,
    float* __restrict__ out)
{
    __shared__ float As[16][65];
    __shared__ float Bs[16][64];

    int tid  = threadIdx.x;
    int row0 = blockIdx.x * 64;
    int col0 = blockIdx.y * 64;
    int tyr  = (tid >> 4) << 2;
    int txc  = (tid & 15) << 2;

    int lr = tid >> 2;
    int lk = (tid & 3) << 2;
    int bk = tid >> 4;
    int bc = (tid & 15) << 2;

    float acc[4][4] = {};

    for (int k0 = 0; k0 < INNER; k0 += 16) {
        float4 av = *(const float4*)&g_Ao[(size_t)(row0 + lr) * INNER + k0 + lk];
        As[lk + 0][lr] = av.x; As[lk + 1][lr] = av.y;
        As[lk + 2][lr] = av.z; As[lk + 3][lr] = av.w;
        *(float4*)&Bs[bk][bc] = *(const float4*)&Wo[(size_t)(k0 + bk) * QD + col0 + bc];
        __syncthreads();
        #pragma unroll
        for (int k = 0; k < 16; k++) {
            float4 bv = *(float4*)&Bs[k][txc];
            float a0 = As[k][tyr], a1 = As[k][tyr + 1];
            float a2 = As[k][tyr + 2], a3 = As[k][tyr + 3];
            acc[0][0] += a0 * bv.x; acc[0][1] += a0 * bv.y; acc[0][2] += a0 * bv.z; acc[0][3] += a0 * bv.w;
            acc[1][0] += a1 * bv.x; acc[1][1] += a1 * bv.y; acc[1][2] += a1 * bv.z; acc[1][3] += a1 * bv.w;
            acc[2][0] += a2 * bv.x; acc[2][1] += a2 * bv.y; acc[2][2] += a2 * bv.z; acc[2][3] += a2 * bv.w;
            acc[3][0] += a3 * bv.x; acc[3][1] += a3 * bv.y; acc[3][2] += a3 * bv.z; acc[3][3] += a3 * bv.w;
        }
        __syncthreads();
    }

    float4 bias = *(const float4*)&bo[col0 + txc];
    #pragma unroll
    for (int i = 0; i < 4; i++) {
        int R = row0 + tyr + i;
        float4 o = make_float4(acc[i][0] + bias.x, acc[i][1] + bias.y,
                               acc[i][2] + bias.z, acc[i][3] + bias.w);
        *(float4*)&out[(size_t)R * QD + col0 + txc] = o;
    }
}

// ---------------------------------------------------------------------------
extern "C" void kernel_launch(void* const* d_in, const int* in_sizes, int n_in,
                              void* d_out, int out_size)
{
    const float* x1  = (const float*)d_in[0];
    const float* x2  = (const float*)d_in[1];
    const float* ctx = (const float*)d_in[2];
    const float* Wq  = (const float*)d_in[3];
    const float* Wq2 = (const float*)d_in[4];
    const float* Wk  = (const float*)d_in[5];
    const float* Wv  = (const float*)d_in[6];
    const float* Wo  = (const float*)d_in[7];
    const float* bo  = (const float*)d_in[8];
    float* out = (float*)d_out;

    // 1) projections: Q, Q2, K, V
    proj_kernel<<<dim3(128, 4, 4), 256>>>(x1, x2, ctx, Wq, Wq2, Wk, Wv);

    // 2) dual-softmax flash attention
    const int smem_bytes = (6 * 64 * SP + 6 * 64) * sizeof(float);  // ~106 KB
    cudaFuncSetAttribute(attn_kernel, cudaFuncAttributeMaxDynamicSharedMemorySize, smem_bytes);
    attn_kernel<<<dim3(32, 16), 256, smem_bytes>>>();

    // 3) output projection + bias
    out_proj_kernel<<<dim3(128, 8), 256>>>(Wo, bo, out);
}

// round 4
// speedup vs baseline: 2.4055x; 2.4055x over previous
#include <cuda_runtime.h>
#include <cstdint>

#define NB 4
#define NH 4
#define DH 64
#define ND 2048
#define QD 512
#define INNER 256
#define SP 68   // smem pitch in floats: bank = (4*grp+qd)%32 -> conflict-free frags

// Scratch (allocation-free: __device__ globals)
__device__ float g_Q [NB*NH*ND*DH];
__device__ float g_Q2[NB*NH*ND*DH];
__device__ float g_K [NB*NH*ND*DH];
__device__ float g_V [NB*NH*ND*DH];
__device__ float g_Ao[NB*ND*INNER];

// ---------------------------------------------------------------------------
__device__ __forceinline__ uint32_t f2tf(float x) {
    uint32_t r; asm("cvt.rna.tf32.f32 %0, %1;" : "=r"(r) : "f"(x)); return r;
}
__device__ __forceinline__ float f2tf_f(float x) { return __uint_as_float(f2tf(x)); }

__device__ __forceinline__ void mma8(float* c, const uint32_t* a, const uint32_t* b) {
    asm volatile(
        "mma.sync.aligned.m16n8k8.row.col.f32.tf32.tf32.f32 "
        "{%0,%1,%2,%3}, {%4,%5,%6,%7}, {%8,%9}, {%0,%1,%2,%3};\n"
        : "+f"(c[0]), "+f"(c[1]), "+f"(c[2]), "+f"(c[3])
        : "r"(a[0]), "r"(a[1]), "r"(a[2]), "r"(a[3]), "r"(b[0]), "r"(b[1]));
}

// ---------------------------------------------------------------------------
// Projection GEMM (tf32 MMA): C = A[8192,512] @ W[512,256], head-split output.
// CTA tile: 128 rows x 64 cols. 256 threads = 8 warps, warp w -> rows 16w.
// ---------------------------------------------------------------------------
__global__ __launch_bounds__(256) void proj_mma_kernel(
    const float* __restrict__ x1, const float* __restrict__ x2,
    const float* __restrict__ ctx,
    const float* __restrict__ Wq, const float* __restrict__ Wq2,
    const float* __restrict__ Wk, const float* __restrict__ Wv)
{
    extern __shared__ float sm[];
    float* As = sm;             // 128 x SP
    float* Ws = sm + 128 * SP;  // 64 x SP

    const float* A; const float* W; float* C;
    int which = blockIdx.z;
    if      (which == 0) { A = x1;  W = Wq;  C = g_Q;  }
    else if (which == 1) { A = x2;  W = Wq2; C = g_Q2; }
    else if (which == 2) { A = ctx; W = Wk;  C = g_K;  }
    else                 { A = ctx; W = Wv;  C = g_V;  }

    int tid  = threadIdx.x;
    int wid  = tid >> 5, lane = tid & 31, grp = lane >> 2, qd = lane & 3;
    int row0 = blockIdx.x * 128;
    int col0 = blockIdx.y * 64;
    int r0   = wid * 16;

    float acc[8][4] = {};

    for (int k0 = 0; k0 < QD; k0 += 64) {
        for (int i = tid; i < 128 * 16; i += 256) {
            int r = i >> 4, c4 = (i & 15) << 2;
            float4 v = *(const float4*)&A[(size_t)(row0 + r) * QD + k0 + c4];
            As[r * SP + c4 + 0] = f2tf_f(v.x);
            As[r * SP + c4 + 1] = f2tf_f(v.y);
            As[r * SP + c4 + 2] = f2tf_f(v.z);
            As[r * SP + c4 + 3] = f2tf_f(v.w);
        }
        for (int i = tid; i < 64 * 16; i += 256) {
            int r = i >> 4, c4 = (i & 15) << 2;
            float4 v = *(const float4*)&W[(size_t)(k0 + r) * INNER + col0 + c4];
            Ws[r * SP + c4 + 0] = f2tf_f(v.x);
            Ws[r * SP + c4 + 1] = f2tf_f(v.y);
            Ws[r * SP + c4 + 2] = f2tf_f(v.z);
            Ws[r * SP + c4 + 3] = f2tf_f(v.w);
        }
        __syncthreads();
        #pragma unroll
        for (int kk = 0; kk < 8; kk++) {
            int kb = kk * 8;
            uint32_t a[4];
            a[0] = __float_as_uint(As[(r0 + grp) * SP + kb + qd]);
            a[1] = __float_as_uint(As[(r0 + grp + 8) * SP + kb + qd]);
            a[2] = __float_as_uint(As[(r0 + grp) * SP + kb + qd + 4]);
            a[3] = __float_as_uint(As[(r0 + grp + 8) * SP + kb + qd + 4]);
            #pragma unroll
            for (int j = 0; j < 8; j++) {
                uint32_t b[2];
                b[0] = __float_as_uint(Ws[(kb + qd) * SP + j * 8 + grp]);
                b[1] = __float_as_uint(Ws[(kb + qd + 4) * SP + j * 8 + grp]);
                mma8(acc[j], a, b);
            }
        }
        __syncthreads();
    }

    int h = blockIdx.y;
    #pragma unroll
    for (int j = 0; j < 8; j++) {
        int col = j * 8 + 2 * qd;
        int R = row0 + r0 + grp;
        int b = R >> 11, ni = R & 2047;
        *(float2*)&C[(((size_t)(b * NH + h)) * ND + ni) * DH + col] =
            make_float2(acc[j][0], acc[j][1]);
        R += 8; b = R >> 11; ni = R & 2047;
        *(float2*)&C[(((size_t)(b * NH + h)) * ND + ni) * DH + col] =
            make_float2(acc[j][2], acc[j][3]);
    }
}

// ---------------------------------------------------------------------------
// Dual-softmax flash attention with tf32 MMA.
// CTA: 64 queries x 64-key tiles, 256 threads. Warps 0-3: (Q,S1,O1),
// warps 4-7: (Q2,S2,O2). K/V tiles shared.
// ---------------------------------------------------------------------------
__device__ __forceinline__ void softmax_part(float* Sr, float* m, float* l,
                                             float* a, int row, int q)
{
    float mx = -1e30f;
    #pragma unroll
    for (int c = 0; c < 16; c++) mx = fmaxf(mx, Sr[c]);
    mx = fmaxf(mx, __shfl_xor_sync(0xffffffffu, mx, 1));
    mx = fmaxf(mx, __shfl_xor_sync(0xffffffffu, mx, 2));
    float mo = m[row], mn = fmaxf(mo, mx);
    float s = 0.f;
    #pragma unroll
    for (int c = 0; c < 16; c++) { float p = __expf(Sr[c] - mn); Sr[c] = p; s += p; }
    s += __shfl_xor_sync(0xffffffffu, s, 1);
    s += __shfl_xor_sync(0xffffffffu, s, 2);
    if (q == 0) {
        float al = __expf(mo - mn);
        l[row] = l[row] * al + s; m[row] = mn; a[row] = al;
    }
}

__global__ __launch_bounds__(256, 2) void attn_mma_kernel()
{
    extern __shared__ float sm[];
    float* Qs  = sm;             // 64 x SP (pre-scaled by 0.125, tf32)
    float* Q2s = Qs  + 64 * SP;
    float* Ks  = Q2s + 64 * SP;
    float* Vs  = Ks  + 64 * SP;
    float* S1  = Vs  + 64 * SP;
    float* S2  = S1  + 64 * SP;
    float* st  = S2  + 64 * SP;  // m1 l1 a1 m2 l2 a2
    float* m1 = st, *l1 = st + 64, *a1 = st + 128;
    float* m2 = st + 192, *l2 = st + 256, *a2 = st + 320;

    int tid = threadIdx.x;
    int wid = tid >> 5, lane = tid & 31, grp = lane >> 2, qd = lane & 3;
    int half = wid >> 2;    // 0: stream 1, 1: stream 2
    int wg   = wid & 3;
    int r0   = wg * 16;

    int bh = blockIdx.y, i0 = blockIdx.x * 64;
    const float* Qg  = g_Q  + ((size_t)bh * ND + i0) * DH;
    const float* Q2g = g_Q2 + ((size_t)bh * ND + i0) * DH;
    const float* Kg  = g_K  + (size_t)bh * ND * DH;
    const float* Vg  = g_V  + (size_t)bh * ND * DH;

    for (int i = tid; i < 64 * 16; i += 256) {
        int r = i >> 4, c4 = (i & 15) << 2;
        float4 v = *(const float4*)&Qg[(size_t)r * DH + c4];
        Qs[r * SP + c4 + 0] = f2tf_f(v.x * 0.125f);
        Qs[r * SP + c4 + 1] = f2tf_f(v.y * 0.125f);
        Qs[r * SP + c4 + 2] = f2tf_f(v.z * 0.125f);
        Qs[r * SP + c4 + 3] = f2tf_f(v.w * 0.125f);
        float4 u = *(const float4*)&Q2g[(size_t)r * DH + c4];
        Q2s[r * SP + c4 + 0] = f2tf_f(u.x * 0.125f);
        Q2s[r * SP + c4 + 1] = f2tf_f(u.y * 0.125f);
        Q2s[r * SP + c4 + 2] = f2tf_f(u.z * 0.125f);
        Q2s[r * SP + c4 + 3] = f2tf_f(u.w * 0.125f);
    }
    if (tid < 64) { m1[tid] = -1e30f; l1[tid] = 0.f; m2[tid] = -1e30f; l2[tid] = 0.f; }

    float* Qsel = half ? Q2s : Qs;
    float* Ssel = half ? S2  : S1;
    float O[8][4] = {};

    for (int kt = 0; kt < 32; kt++) {
        size_t base = (size_t)kt * 64 * DH;
        for (int i = tid; i < 64 * 16; i += 256) {
            int r = i >> 4, c4 = (i & 15) << 2;
            float4 v = *(const float4*)&Kg[base + (size_t)r * DH + c4];
            Ks[r * SP + c4 + 0] = f2tf_f(v.x);
            Ks[r * SP + c4 + 1] = f2tf_f(v.y);
            Ks[r * SP + c4 + 2] = f2tf_f(v.z);
            Ks[r * SP + c4 + 3] = f2tf_f(v.w);
            float4 u = *(const float4*)&Vg[base + (size_t)r * DH + c4];
            Vs[r * SP + c4 + 0] = f2tf_f(u.x);
            Vs[r * SP + c4 + 1] = f2tf_f(u.y);
            Vs[r * SP + c4 + 2] = f2tf_f(u.z);
            Vs[r * SP + c4 + 3] = f2tf_f(u.w);
        }
        __syncthreads();

        // ---- S = (scaled Q) K^T ----
        {
            float sacc[8][4] = {};
            #pragma unroll
            for (int kk = 0; kk < 8; kk++) {
                int kb = kk * 8;
                uint32_t a[4];
                a[0] = __float_as_uint(Qsel[(r0 + grp) * SP + kb + qd]);
                a[1] = __float_as_uint(Qsel[(r0 + grp + 8) * SP + kb + qd]);
                a[2] = __float_as_uint(Qsel[(r0 + grp) * SP + kb + qd + 4]);
                a[3] = __float_as_uint(Qsel[(r0 + grp + 8) * SP + kb + qd + 4]);
                #pragma unroll
                for (int j = 0; j < 8; j++) {
                    uint32_t b[2];
                    b[0] = __float_as_uint(Ks[(j * 8 + grp) * SP + kb + qd]);
                    b[1] = __float_as_uint(Ks[(j * 8 + grp) * SP + kb + qd + 4]);
                    mma8(sacc[j], a, b);
                }
            }
            #pragma unroll
            for (int j = 0; j < 8; j++) {
                int col = j * 8 + 2 * qd;
                *(float2*)&Ssel[(r0 + grp) * SP + col]     = make_float2(sacc[j][0], sacc[j][1]);
                *(float2*)&Ssel[(r0 + grp + 8) * SP + col] = make_float2(sacc[j][2], sacc[j][3]);
            }
        }
        __syncthreads();

        // ---- online softmax on both matrices (4 threads / row) ----
        {
            int row = tid >> 2, q = tid & 3;
            softmax_part(S1 + row * SP + q * 16, m1, l1, a1, row, q);
            softmax_part(S2 + row * SP + q * 16, m2, l2, a2, row, q);
        }
        __syncthreads();

        // ---- O = O*alpha + P V ----
        {
            float* as_ = half ? a2 : a1;
            float alo = as_[r0 + grp], ahi = as_[r0 + grp + 8];
            #pragma unroll
            for (int j = 0; j < 8; j++) {
                O[j][0] *= alo; O[j][1] *= alo; O[j][2] *= ahi; O[j][3] *= ahi;
            }
            #pragma unroll
            for (int kk = 0; kk < 8; kk++) {
                int kb = kk * 8;
                uint32_t a[4];
                a[0] = f2tf(Ssel[(r0 + grp) * SP + kb + qd]);
                a[1] = f2tf(Ssel[(r0 + grp + 8) * SP + kb + qd]);
                a[2] = f2tf(Ssel[(r0 + grp) * SP + kb + qd + 4]);
                a[3] = f2tf(Ssel[(r0 + grp + 8) * SP + kb + qd + 4]);
                #pragma unroll
                for (int j = 0; j < 8; j++) {
                    uint32_t b[2];
                    b[0] = __float_as_uint(Vs[(kb + qd) * SP + j * 8 + grp]);
                    b[1] = __float_as_uint(Vs[(kb + qd + 4) * SP + j * 8 + grp]);
                    mma8(O[j], a, b);
                }
            }
        }
        __syncthreads();
    }

    // ---- epilogue: out = 0.3*O1/l1 + 0.7*O2/l2, staged through S1 ----
    if (half == 0) {
        float ilo = 0.3f / l1[r0 + grp], ihi = 0.3f / l1[r0 + grp + 8];
        #pragma unroll
        for (int j = 0; j < 8; j++) {
            int col = j * 8 + 2 * qd;
            *(float2*)&S1[(r0 + grp) * SP + col]     = make_float2(O[j][0] * ilo, O[j][1] * ilo);
            *(float2*)&S1[(r0 + grp + 8) * SP + col] = make_float2(O[j][2] * ihi, O[j][3] * ihi);
        }
    }
    __syncthreads();
    if (half == 1) {
        float ilo = 0.7f / l2[r0 + grp], ihi = 0.7f / l2[r0 + grp + 8];
        int b = bh >> 2, h = bh & 3;
        float* outp = g_Ao + ((size_t)b * ND + i0) * INNER + h * DH;
        #pragma unroll
        for (int j = 0; j < 8; j++) {
            int col = j * 8 + 2 * qd;
            float2 p = *(float2*)&S1[(r0 + grp) * SP + col];
            *(float2*)&outp[(size_t)(r0 + grp) * INNER + col] =
                make_float2(p.x + O[j][0] * ilo, p.y + O[j][1] * ilo);
            p = *(float2*)&S1[(r0 + grp + 8) * SP + col];
            *(float2*)&outp[(size_t)(r0 + grp + 8) * INNER + col] =
                make_float2(p.x + O[j][2] * ihi, p.y + O[j][3] * ihi);
        }
    }
}

// ---------------------------------------------------------------------------
// Output projection (tf32 MMA): out = Ao[8192,256] @ Wo[256,512] + bo
// ---------------------------------------------------------------------------
__global__ __launch_bounds__(256) void outproj_mma_kernel(
    const float* __restrict__ Wo, const float* __restrict__ bo,
    float* __restrict__ out)
{
    extern __shared__ float sm[];
    float* As = sm;             // 128 x SP
    float* Ws = sm + 128 * SP;  // 64 x SP

    int tid  = threadIdx.x;
    int wid  = tid >> 5, lane = tid & 31, grp = lane >> 2, qd = lane & 3;
    int row0 = blockIdx.x * 128;
    int col0 = blockIdx.y * 64;
    int r0   = wid * 16;

    float acc[8][4] = {};

    for (int k0 = 0; k0 < INNER; k0 += 64) {
        for (int i = tid; i < 128 * 16; i += 256) {
            int r = i >> 4, c4 = (i & 15) << 2;
            float4 v = *(const float4*)&g_Ao[(size_t)(row0 + r) * INNER + k0 + c4];
            As[r * SP + c4 + 0] = f2tf_f(v.x);
            As[r * SP + c4 + 1] = f2tf_f(v.y);
            As[r * SP + c4 + 2] = f2tf_f(v.z);
            As[r * SP + c4 + 3] = f2tf_f(v.w);
        }
        for (int i = tid; i < 64 * 16; i += 256) {
            int r = i >> 4, c4 = (i & 15) << 2;
            float4 v = *(const float4*)&Wo[(size_t)(k0 + r) * QD + col0 + c4];
            Ws[r * SP + c4 + 0] = f2tf_f(v.x);
            Ws[r * SP + c4 + 1] = f2tf_f(v.y);
            Ws[r * SP + c4 + 2] = f2tf_f(v.z);
            Ws[r * SP + c4 + 3] = f2tf_f(v.w);
        }
        __syncthreads();
        #pragma unroll
        for (int kk = 0; kk < 8; kk++) {
            int kb = kk * 8;
            uint32_t a[4];
            a[0] = __float_as_uint(As[(r0 + grp) * SP + kb + qd]);
            a[1] = __float_as_uint(As[(r0 + grp + 8) * SP + kb + qd]);
            a[2] = __float_as_uint(As[(r0 + grp) * SP + kb + qd + 4]);
            a[3] = __float_as_uint(As[(r0 + grp + 8) * SP + kb + qd + 4]);
            #pragma unroll
            for (int j = 0; j < 8; j++) {
                uint32_t b[2];
                b[0] = __float_as_uint(Ws[(kb + qd) * SP + j * 8 + grp]);
                b[1] = __float_as_uint(Ws[(kb + qd + 4) * SP + j * 8 + grp]);
                mma8(acc[j], a, b);
            }
        }
        __syncthreads();
    }

    #pragma unroll
    for (int j = 0; j < 8; j++) {
        int col = j * 8 + 2 * qd;
        float b0 = bo[col0 + col], b1 = bo[col0 + col + 1];
        int R = row0 + r0 + grp;
        *(float2*)&out[(size_t)R * QD + col0 + col] =
            make_float2(acc[j][0] + b0, acc[j][1] + b1);
        R += 8;
        *(float2*)&out[(size_t)R * QD + col0 + col] =
            make_float2(acc[j][2] + b0, acc[j][3] + b1);
    }
}

// ---------------------------------------------------------------------------
extern "C" void kernel_launch(void* const* d_in, const int* in_sizes, int n_in,
                              void* d_out, int out_size)
{
    const float* x1  = (const float*)d_in[0];
    const float* x2  = (const float*)d_in[1];
    const float* ctx = (const float*)d_in[2];
    const float* Wq  = (const float*)d_in[3];
    const float* Wq2 = (const float*)d_in[4];
    const float* Wk  = (const float*)d_in[5];
    const float* Wv  = (const float*)d_in[6];
    const float* Wo  = (const float*)d_in[7];
    const float* bo  = (const float*)d_in[8];
    float* out = (float*)d_out;

    const int gemm_smem = (128 * SP + 64 * SP) * sizeof(float);   // ~51 KB
    const int attn_smem = (6 * 64 * SP + 6 * 64) * sizeof(float); // ~104 KB

    // Unconditional (no static guards — harness rule); idempotent host-side calls.
    cudaFuncSetAttribute(proj_mma_kernel,
        cudaFuncAttributeMaxDynamicSharedMemorySize, gemm_smem);
    cudaFuncSetAttribute(attn_mma_kernel,
        cudaFuncAttributeMaxDynamicSharedMemorySize, attn_smem);
    cudaFuncSetAttribute(outproj_mma_kernel,
        cudaFuncAttributeMaxDynamicSharedMemorySize, gemm_smem);

    // 1) projections: Q, Q2, K, V (tf32 MMA)
    proj_mma_kernel<<<dim3(64, 4, 4), 256, gemm_smem>>>(x1, x2, ctx, Wq, Wq2, Wk, Wv);

    // 2) dual-softmax flash attention (tf32 MMA)
    attn_mma_kernel<<<dim3(32, 16), 256, attn_smem>>>();

    // 3) output projection + bias (tf32 MMA)
    outproj_mma_kernel<<<dim3(64, 8), 256, gemm_smem>>>(Wo, bo, out);
}

// round 6
// speedup vs baseline: 2.7650x; 1.1495x over previous
#include <cuda_runtime.h>
#include <cstdint>

#define NB 4
#define NH 4
#define DH 64
#define ND 2048
#define QD 512
#define INNER 256
#define SP 68    // pitch for row-indexed ([n][k]) tiles: banks (4*grp+qd)%32 conflict-free
#define SPB 72   // pitch for k-indexed ([k][n]) tiles: banks (8*qd+grp)%32 conflict-free

// Scratch (allocation-free: __device__ globals)
__device__ float g_Q [NB*NH*ND*DH];
__device__ float g_Q2[NB*NH*ND*DH];
__device__ float g_K [NB*NH*ND*DH];
__device__ float g_V [NB*NH*ND*DH];
__device__ float g_Ao[NB*ND*INNER];

// ---------------------------------------------------------------------------
__device__ __forceinline__ uint32_t f2tf(float x) {
    uint32_t r; asm("cvt.rna.tf32.f32 %0, %1;" : "=r"(r) : "f"(x)); return r;
}
__device__ __forceinline__ float f2tf_f(float x) { return __uint_as_float(f2tf(x)); }

__device__ __forceinline__ void mma8(float* c, const uint32_t* a, const uint32_t* b) {
    asm volatile(
        "mma.sync.aligned.m16n8k8.row.col.f32.tf32.tf32.f32 "
        "{%0,%1,%2,%3}, {%4,%5,%6,%7}, {%8,%9}, {%0,%1,%2,%3};\n"
        : "+f"(c[0]), "+f"(c[1]), "+f"(c[2]), "+f"(c[3])
        : "r"(a[0]), "r"(a[1]), "r"(a[2]), "r"(a[3]), "r"(b[0]), "r"(b[1]));
}

// ---------------------------------------------------------------------------
// Projection GEMM (tf32 MMA): C = A[8192,512] @ W[512,256], head-split output.
// CTA tile: 128 rows x 64 cols. 8 warps, warp w -> rows 16w.
// ---------------------------------------------------------------------------
__global__ __launch_bounds__(256) void proj_mma_kernel(
    const float* __restrict__ x1, const float* __restrict__ x2,
    const float* __restrict__ ctx,
    const float* __restrict__ Wq, const float* __restrict__ Wq2,
    const float* __restrict__ Wk, const float* __restrict__ Wv)
{
    extern __shared__ float sm[];
    float* As = sm;             // 128 x SP (row-indexed)
    float* Ws = sm + 128 * SP;  // 64 x SPB (k-indexed)

    const float* A; const float* W; float* C;
    int which = blockIdx.z;
    if      (which == 0) { A = x1;  W = Wq;  C = g_Q;  }
    else if (which == 1) { A = x2;  W = Wq2; C = g_Q2; }
    else if (which == 2) { A = ctx; W = Wk;  C = g_K;  }
    else                 { A = ctx; W = Wv;  C = g_V;  }

    int tid  = threadIdx.x;
    int wid  = tid >> 5, lane = tid & 31, grp = lane >> 2, qd = lane & 3;
    int row0 = blockIdx.x * 128;
    int col0 = blockIdx.y * 64;
    int r0   = wid * 16;

    float acc[8][4] = {};

    for (int k0 = 0; k0 < QD; k0 += 64) {
        for (int i = tid; i < 128 * 16; i += 256) {
            int r = i >> 4, c4 = (i & 15) << 2;
            float4 v = *(const float4*)&A[(size_t)(row0 + r) * QD + k0 + c4];
            As[r * SP + c4 + 0] = f2tf_f(v.x);
            As[r * SP + c4 + 1] = f2tf_f(v.y);
            As[r * SP + c4 + 2] = f2tf_f(v.z);
            As[r * SP + c4 + 3] = f2tf_f(v.w);
        }
        for (int i = tid; i < 64 * 16; i += 256) {
            int r = i >> 4, c4 = (i & 15) << 2;
            float4 v = *(const float4*)&W[(size_t)(k0 + r) * INNER + col0 + c4];
            Ws[r * SPB + c4 + 0] = f2tf_f(v.x);
            Ws[r * SPB + c4 + 1] = f2tf_f(v.y);
            Ws[r * SPB + c4 + 2] = f2tf_f(v.z);
            Ws[r * SPB + c4 + 3] = f2tf_f(v.w);
        }
        __syncthreads();
        #pragma unroll
        for (int kk = 0; kk < 8; kk++) {
            int kb = kk * 8;
            uint32_t a[4];
            a[0] = __float_as_uint(As[(r0 + grp) * SP + kb + qd]);
            a[1] = __float_as_uint(As[(r0 + grp + 8) * SP + kb + qd]);
            a[2] = __float_as_uint(As[(r0 + grp) * SP + kb + qd + 4]);
            a[3] = __float_as_uint(As[(r0 + grp + 8) * SP + kb + qd + 4]);
            #pragma unroll
            for (int j = 0; j < 8; j++) {
                uint32_t b[2];
                b[0] = __float_as_uint(Ws[(kb + qd) * SPB + j * 8 + grp]);
                b[1] = __float_as_uint(Ws[(kb + qd + 4) * SPB + j * 8 + grp]);
                mma8(acc[j], a, b);
            }
        }
        __syncthreads();
    }

    int h = blockIdx.y;
    #pragma unroll
    for (int j = 0; j < 8; j++) {
        int col = j * 8 + 2 * qd;
        int R = row0 + r0 + grp;
        int b = R >> 11, ni = R & 2047;
        *(float2*)&C[(((size_t)(b * NH + h)) * ND + ni) * DH + col] =
            make_float2(acc[j][0], acc[j][1]);
        R += 8; b = R >> 11; ni = R & 2047;
        *(float2*)&C[(((size_t)(b * NH + h)) * ND + ni) * DH + col] =
            make_float2(acc[j][2], acc[j][3]);
    }
}

// ---------------------------------------------------------------------------
// Dual-softmax flash attention, register-resident (FA2 style).
// CTA: 64 queries x 64-key tiles, 256 threads. Warps 0-3: stream1 (Q,O1),
// warps 4-7: stream2 (Q2,O2). K/V tiles shared in smem. S stays in registers;
// softmax via quad shuffles; P transposed to A-fragments via quad shuffles.
// ---------------------------------------------------------------------------
__global__ __launch_bounds__(256) void attn_mma_kernel()
{
    __shared__ float Ks[64 * SP];    // [key][d]  (row-indexed, pitch 68)
    __shared__ float Vs[64 * SPB];   // [key][d] used as B[k=key][n=d] (pitch 72)

    int tid = threadIdx.x;
    int wid = tid >> 5, lane = tid & 31, grp = lane >> 2, qd = lane & 3;
    int half = wid >> 2;    // 0: stream 1, 1: stream 2
    int wg   = wid & 3;
    int r0   = wg * 16;

    int bh = blockIdx.y, i0 = blockIdx.x * 64;
    const float* Qg = (half ? g_Q2 : g_Q) + ((size_t)bh * ND + i0) * DH;
    const float* Kg = g_K + (size_t)bh * ND * DH;
    const float* Vg = g_V + (size_t)bh * ND * DH;

    // Preload Q fragments (scale folded in): 32 regs
    uint32_t qf[8][4];
    {
        const float* q0 = Qg + (size_t)(r0 + grp) * DH;
        const float* q1 = Qg + (size_t)(r0 + grp + 8) * DH;
        #pragma unroll
        for (int kk = 0; kk < 8; kk++) {
            qf[kk][0] = f2tf(q0[kk * 8 + qd]     * 0.125f);
            qf[kk][1] = f2tf(q1[kk * 8 + qd]     * 0.125f);
            qf[kk][2] = f2tf(q0[kk * 8 + qd + 4] * 0.125f);
            qf[kk][3] = f2tf(q1[kk * 8 + qd + 4] * 0.125f);
        }
    }

    float O[8][4] = {};
    float m_lo = -1e30f, m_hi = -1e30f, l_lo = 0.f, l_hi = 0.f;

    for (int kt = 0; kt < 32; kt++) {
        size_t base = (size_t)kt * 64 * DH;
        for (int i = tid; i < 64 * 16; i += 256) {
            int r = i >> 4, c4 = (i & 15) << 2;
            float4 v = *(const float4*)&Kg[base + (size_t)r * DH + c4];
            Ks[r * SP + c4 + 0] = f2tf_f(v.x);
            Ks[r * SP + c4 + 1] = f2tf_f(v.y);
            Ks[r * SP + c4 + 2] = f2tf_f(v.z);
            Ks[r * SP + c4 + 3] = f2tf_f(v.w);
            float4 u = *(const float4*)&Vg[base + (size_t)r * DH + c4];
            Vs[r * SPB + c4 + 0] = f2tf_f(u.x);
            Vs[r * SPB + c4 + 1] = f2tf_f(u.y);
            Vs[r * SPB + c4 + 2] = f2tf_f(u.z);
            Vs[r * SPB + c4 + 3] = f2tf_f(u.w);
        }
        __syncthreads();

        // ---- S = (scaled Q) K^T, in registers ----
        float sacc[8][4] = {};
        #pragma unroll
        for (int kk = 0; kk < 8; kk++) {
            int kb = kk * 8;
            #pragma unroll
            for (int j = 0; j < 8; j++) {
                uint32_t b[2];
                b[0] = __float_as_uint(Ks[(j * 8 + grp) * SP + kb + qd]);
                b[1] = __float_as_uint(Ks[(j * 8 + grp) * SP + kb + qd + 4]);
                mma8(sacc[j], qf[kk], b);
            }
        }

        // ---- register online softmax (quad-wide rows) ----
        {
            float mx_lo = -1e30f, mx_hi = -1e30f;
            #pragma unroll
            for (int j = 0; j < 8; j++) {
                mx_lo = fmaxf(mx_lo, fmaxf(sacc[j][0], sacc[j][1]));
                mx_hi = fmaxf(mx_hi, fmaxf(sacc[j][2], sacc[j][3]));
            }
            mx_lo = fmaxf(mx_lo, __shfl_xor_sync(0xffffffffu, mx_lo, 1));
            mx_lo = fmaxf(mx_lo, __shfl_xor_sync(0xffffffffu, mx_lo, 2));
            mx_hi = fmaxf(mx_hi, __shfl_xor_sync(0xffffffffu, mx_hi, 1));
            mx_hi = fmaxf(mx_hi, __shfl_xor_sync(0xffffffffu, mx_hi, 2));
            float mn_lo = fmaxf(m_lo, mx_lo), mn_hi = fmaxf(m_hi, mx_hi);
            float al_lo = __expf(m_lo - mn_lo), al_hi = __expf(m_hi - mn_hi);
            m_lo = mn_lo; m_hi = mn_hi;
            float s_lo = 0.f, s_hi = 0.f;
            #pragma unroll
            for (int j = 0; j < 8; j++) {
                sacc[j][0] = __expf(sacc[j][0] - mn_lo); s_lo += sacc[j][0];
                sacc[j][1] = __expf(sacc[j][1] - mn_lo); s_lo += sacc[j][1];
                sacc[j][2] = __expf(sacc[j][2] - mn_hi); s_hi += sacc[j][2];
                sacc[j][3] = __expf(sacc[j][3] - mn_hi); s_hi += sacc[j][3];
            }
            s_lo += __shfl_xor_sync(0xffffffffu, s_lo, 1);
            s_lo += __shfl_xor_sync(0xffffffffu, s_lo, 2);
            s_hi += __shfl_xor_sync(0xffffffffu, s_hi, 1);
            s_hi += __shfl_xor_sync(0xffffffffu, s_hi, 2);
            l_lo = l_lo * al_lo + s_lo;
            l_hi = l_hi * al_hi + s_hi;
            #pragma unroll
            for (int j = 0; j < 8; j++) {
                O[j][0] *= al_lo; O[j][1] *= al_lo;
                O[j][2] *= al_hi; O[j][3] *= al_hi;
            }
        }

        // ---- O += P V : transpose P (C-layout -> A-layout) via quad shuffles ----
        {
            int src  = qd >> 1;       // within-quad source lane (cols 2s, 2s+1)
            int src2 = src + 2;       // for cols qd+4
            bool odd = qd & 1;
            #pragma unroll
            for (int kk = 0; kk < 8; kk++) {
                float x0 = __shfl_sync(0xffffffffu, sacc[kk][0], src, 4);
                float x1 = __shfl_sync(0xffffffffu, sacc[kk][1], src, 4);
                float x2 = __shfl_sync(0xffffffffu, sacc[kk][2], src, 4);
                float x3 = __shfl_sync(0xffffffffu, sacc[kk][3], src, 4);
                float y0 = __shfl_sync(0xffffffffu, sacc[kk][0], src2, 4);
                float y1 = __shfl_sync(0xffffffffu, sacc[kk][1], src2, 4);
                float y2 = __shfl_sync(0xffffffffu, sacc[kk][2], src2, 4);
                float y3 = __shfl_sync(0xffffffffu, sacc[kk][3], src2, 4);
                uint32_t a[4];
                a[0] = f2tf(odd ? x1 : x0);   // P[grp   ][kb+qd]
                a[1] = f2tf(odd ? x3 : x2);   // P[grp+8 ][kb+qd]
                a[2] = f2tf(odd ? y1 : y0);   // P[grp   ][kb+qd+4]
                a[3] = f2tf(odd ? y3 : y2);   // P[grp+8 ][kb+qd+4]
                int kb = kk * 8;
                #pragma unroll
                for (int j = 0; j < 8; j++) {
                    uint32_t b[2];
                    b[0] = __float_as_uint(Vs[(kb + qd) * SPB + j * 8 + grp]);
                    b[1] = __float_as_uint(Vs[(kb + qd + 4) * SPB + j * 8 + grp]);
                    mma8(O[j], a, b);
                }
            }
        }
        __syncthreads();
    }

    // ---- epilogue: out = 0.3*O1/l1 + 0.7*O2/l2, staged through Ks ----
    if (half == 0) {
        float s_lo = 0.3f / l_lo, s_hi = 0.3f / l_hi;
        #pragma unroll
        for (int j = 0; j < 8; j++) {
            int col = j * 8 + 2 * qd;
            *(float2*)&Ks[(r0 + grp) * SP + col] =
                make_float2(O[j][0] * s_lo, O[j][1] * s_lo);
            *(float2*)&Ks[(r0 + grp + 8) * SP + col] =
                make_float2(O[j][2] * s_hi, O[j][3] * s_hi);
        }
    }
    __syncthreads();
    if (half == 1) {
        float s_lo = 0.7f / l_lo, s_hi = 0.7f / l_hi;
        int b = bh >> 2, h = bh & 3;
        float* outp = g_Ao + ((size_t)b * ND + i0) * INNER + h * DH;
        #pragma unroll
        for (int j = 0; j < 8; j++) {
            int col = j * 8 + 2 * qd;
            float2 p = *(float2*)&Ks[(r0 + grp) * SP + col];
            *(float2*)&outp[(size_t)(r0 + grp) * INNER + col] =
                make_float2(p.x + O[j][0] * s_lo, p.y + O[j][1] * s_lo);
            p = *(float2*)&Ks[(r0 + grp + 8) * SP + col];
            *(float2*)&outp[(size_t)(r0 + grp + 8) * INNER + col] =
                make_float2(p.x + O[j][2] * s_hi, p.y + O[j][3] * s_hi);
        }
    }
}

// ---------------------------------------------------------------------------
// Output projection (tf32 MMA): out = Ao[8192,256] @ Wo[256,512] + bo
// ---------------------------------------------------------------------------
__global__ __launch_bounds__(256) void outproj_mma_kernel(
    const float* __restrict__ Wo, const float* __restrict__ bo,
    float* __restrict__ out)
{
    extern __shared__ float sm[];
    float* As = sm;             // 128 x SP
    float* Ws = sm + 128 * SP;  // 64 x SPB

    int tid  = threadIdx.x;
    int wid  = tid >> 5, lane = tid & 31, grp = lane >> 2, qd = lane & 3;
    int row0 = blockIdx.x * 128;
    int col0 = blockIdx.y * 64;
    int r0   = wid * 16;

    float acc[8][4] = {};

    for (int k0 = 0; k0 < INNER; k0 += 64) {
        for (int i = tid; i < 128 * 16; i += 256) {
            int r = i >> 4, c4 = (i & 15) << 2;
            float4 v = *(const float4*)&g_Ao[(size_t)(row0 + r) * INNER + k0 + c4];
            As[r * SP + c4 + 0] = f2tf_f(v.x);
            As[r * SP + c4 + 1] = f2tf_f(v.y);
            As[r * SP + c4 + 2] = f2tf_f(v.z);
            As[r * SP + c4 + 3] = f2tf_f(v.w);
        }
        for (int i = tid; i < 64 * 16; i += 256) {
            int r = i >> 4, c4 = (i & 15) << 2;
            float4 v = *(const float4*)&Wo[(size_t)(k0 + r) * QD + col0 + c4];
            Ws[r * SPB + c4 + 0] = f2tf_f(v.x);
            Ws[r * SPB + c4 + 1] = f2tf_f(v.y);
            Ws[r * SPB + c4 + 2] = f2tf_f(v.z);
            Ws[r * SPB + c4 + 3] = f2tf_f(v.w);
        }
        __syncthreads();
        #pragma unroll
        for (int kk = 0; kk < 8; kk++) {
            int kb = kk * 8;
            uint32_t a[4];
            a[0] = __float_as_uint(As[(r0 + grp) * SP + kb + qd]);
            a[1] = __float_as_uint(As[(r0 + grp + 8) * SP + kb + qd]);
            a[2] = __float_as_uint(As[(r0 + grp) * SP + kb + qd + 4]);
            a[3] = __float_as_uint(As[(r0 + grp + 8) * SP + kb + qd + 4]);
            #pragma unroll
            for (int j = 0; j < 8; j++) {
                uint32_t b[2];
                b[0] = __float_as_uint(Ws[(kb + qd) * SPB + j * 8 + grp]);
                b[1] = __float_as_uint(Ws[(kb + qd + 4) * SPB + j * 8 + grp]);
                mma8(acc[j], a, b);
            }
        }
        __syncthreads();
    }

    #pragma unroll
    for (int j = 0; j < 8; j++) {
        int col = j * 8 + 2 * qd;
        float b0 = bo[col0 + col], b1 = bo[col0 + col + 1];
        int R = row0 + r0 + grp;
        *(float2*)&out[(size_t)R * QD + col0 + col] =
            make_float2(acc[j][0] + b0, acc[j][1] + b1);
        R += 8;
        *(float2*)&out[(size_t)R * QD + col0 + col] =
            make_float2(acc[j][2] + b0, acc[j][3] + b1);
    }
}

// ---------------------------------------------------------------------------
extern "C" void kernel_launch(void* const* d_in, const int* in_sizes, int n_in,
                              void* d_out, int out_size)
{
    const float* x1  = (const float*)d_in[0];
    const float* x2  = (const float*)d_in[1];
    const float* ctx = (const float*)d_in[2];
    const float* Wq  = (const float*)d_in[3];
    const float* Wq2 = (const float*)d_in[4];
    const float* Wk  = (const float*)d_in[5];
    const float* Wv  = (const float*)d_in[6];
    const float* Wo  = (const float*)d_in[7];
    const float* bo  = (const float*)d_in[8];
    float* out = (float*)d_out;

    const int gemm_smem = (128 * SP + 64 * SPB) * sizeof(float);  // ~53 KB

    // Unconditional (no static guards); idempotent host-side calls.
    cudaFuncSetAttribute(proj_mma_kernel,
        cudaFuncAttributeMaxDynamicSharedMemorySize, gemm_smem);
    cudaFuncSetAttribute(outproj_mma_kernel,
        cudaFuncAttributeMaxDynamicSharedMemorySize, gemm_smem);

    // 1) projections: Q, Q2, K, V (tf32 MMA)
    proj_mma_kernel<<<dim3(64, 4, 4), 256, gemm_smem>>>(x1, x2, ctx, Wq, Wq2, Wk, Wv);

    // 2) dual-softmax flash attention (register-resident, tf32 MMA)
    attn_mma_kernel<<<dim3(32, 16), 256>>>();

    // 3) output projection + bias (tf32 MMA)
    outproj_mma_kernel<<<dim3(64, 8), 256, gemm_smem>>>(Wo, bo, out);
}

// round 9
// speedup vs baseline: 3.4041x; 1.2311x over previous
#include <cuda_runtime.h>
#include <cstdint>

#define NB 4
#define NH 4
#define DH 64
#define ND 2048
#define QD 512
#define INNER 256

// attention smem pitches (all chosen so pitch mod 32 == 8 for conflict-free LDS.64)
#define KP   72          // K tile row pitch (words)
#define VPN  136         // V/W blocked layout: per-q-row pitch
#define VBLK 544         // V/W blocked layout: per-8k-block pitch (4*VPN)
#define KTILE (64*KP)    // 4608 words
#define VTILE (8*VBLK)   // 4352 words
#define AP   72          // GEMM As pitch

// Scratch (allocation-free: __device__ globals)
__device__ float g_Q [NB*NH*ND*DH];
__device__ float g_Q2[NB*NH*ND*DH];
__device__ float g_K [NB*NH*ND*DH];   // pair-interleaved columns, tf32-rounded
__device__ float g_V [NB*NH*ND*DH];   // row-pair-blocked layout, tf32-rounded
__device__ float g_Ao[NB*ND*INNER];

// ---------------------------------------------------------------------------
__device__ __forceinline__ uint32_t f2tf(float x) {
    uint32_t r; asm("cvt.rna.tf32.f32 %0, %1;" : "=r"(r) : "f"(x)); return r;
}
__device__ __forceinline__ float f2tf_f(float x) { return __uint_as_float(f2tf(x)); }

// pair-interleave within 8-wide blocks: d -> (d&~7) + 2*(d&3) + ((d>>2)&1)
__device__ __forceinline__ int ilc(int d) {
    return (d & ~7) + 2 * (d & 3) + ((d >> 2) & 1);
}
// V gmem blocked address (within a 32-row group): pairs (n, n+4) interleaved
__device__ __forceinline__ int vadr(int n, int d) {
    return ((n >> 3) << 9) + ((n & 3) << 7) + 2 * d + ((n >> 2) & 1);
}

__device__ __forceinline__ void mma8(float* c, const uint32_t* a, const uint32_t* b) {
    asm volatile(
        "mma.sync.aligned.m16n8k8.row.col.f32.tf32.tf32.f32 "
        "{%0,%1,%2,%3}, {%4,%5,%6,%7}, {%8,%9}, {%0,%1,%2,%3};\n"
        : "+f"(c[0]), "+f"(c[1]), "+f"(c[2]), "+f"(c[3])
        : "r"(a[0]), "r"(a[1]), "r"(a[2]), "r"(a[3]), "r"(b[0]), "r"(b[1]));
}

__device__ __forceinline__ void cpa16(float* dst, const float* src) {
    uint32_t d = (uint32_t)__cvta_generic_to_shared(dst);
    asm volatile("cp.async.cg.shared.global [%0], [%1], 16;" :: "r"(d), "l"(src));
}

// ---------------------------------------------------------------------------
// Projection GEMM (tf32 MMA): C = A[8192,512] @ W[512,256].
// Writes head-split outputs, tf32-pre-rounded; K/V in attention-ready layouts.
// CTA tile: 128 rows x 64 cols. 8 warps.
// ---------------------------------------------------------------------------
__global__ __launch_bounds__(256) void proj_mma_kernel(
    const float* __restrict__ x1, const float* __restrict__ x2,
    const float* __restrict__ ctx,
    const float* __restrict__ Wq, const float* __restrict__ Wq2,
    const float* __restrict__ Wk, const float* __restrict__ Wv)
{
    extern __shared__ float sm[];
    float* As = sm;             // 128 x AP, pair-interleaved k-columns
    float* Ws = sm + 128 * AP;  // blocked k-row layout (VPN/VBLK)

    const float* A; const float* W; float* C;
    int which = blockIdx.z;
    if      (which == 0) { A = x1;  W = Wq;  C = g_Q;  }
    else if (which == 1) { A = x2;  W = Wq2; C = g_Q2; }
    else if (which == 2) { A = ctx; W = Wk;  C = g_K;  }
    else                 { A = ctx; W = Wv;  C = g_V;  }

    int tid  = threadIdx.x;
    int wid  = tid >> 5, lane = tid & 31, grp = lane >> 2, qd = lane & 3;
    int row0 = blockIdx.x * 128;
    int col0 = blockIdx.y * 64;
    int r0   = wid * 16;

    float acc[8][4] = {};

    for (int k0 = 0; k0 < QD; k0 += 64) {
        for (int i = tid; i < 128 * 16; i += 256) {
            int r = i >> 4, c4 = (i & 15) << 2;
            float4 v = *(const float4*)&A[(size_t)(row0 + r) * QD + k0 + c4];
            int base = r * AP + (c4 & ~7) + ((c4 & 4) ? 1 : 0);
            As[base + 0] = f2tf_f(v.x);
            As[base + 2] = f2tf_f(v.y);
            As[base + 4] = f2tf_f(v.z);
            As[base + 6] = f2tf_f(v.w);
        }
        for (int i = tid; i < 64 * 16; i += 256) {
            int r = i >> 4, c4 = (i & 15) << 2;
            float4 v = *(const float4*)&W[(size_t)(k0 + r) * INNER + col0 + c4];
            int base = (r >> 3) * VBLK + (r & 3) * VPN + ((r >> 2) & 1) + 2 * c4;
            Ws[base + 0] = f2tf_f(v.x);
            Ws[base + 2] = f2tf_f(v.y);
            Ws[base + 4] = f2tf_f(v.z);
            Ws[base + 6] = f2tf_f(v.w);
        }
        __syncthreads();
        #pragma unroll
        for (int kk = 0; kk < 8; kk++) {
            int kb = kk * 8;
            float2 alo = *(const float2*)&As[(r0 + grp) * AP + kb + 2 * qd];
            float2 ahi = *(const float2*)&As[(r0 + grp + 8) * AP + kb + 2 * qd];
            uint32_t a[4];
            a[0] = __float_as_uint(alo.x); a[1] = __float_as_uint(ahi.x);
            a[2] = __float_as_uint(alo.y); a[3] = __float_as_uint(ahi.y);
            #pragma unroll
            for (int j = 0; j < 8; j++) {
                float2 bv = *(const float2*)&Ws[kk * VBLK + qd * VPN + 2 * (j * 8 + grp)];
                uint32_t b[2] = { __float_as_uint(bv.x), __float_as_uint(bv.y) };
                mma8(acc[j], a, b);
            }
        }
        __syncthreads();
    }

    int h = blockIdx.y;
    #pragma unroll
    for (int j = 0; j < 8; j++) {
        int col = j * 8 + 2 * qd;
        #pragma unroll
        for (int hf = 0; hf < 2; hf++) {
            int R = row0 + r0 + grp + hf * 8;
            int b = R >> 11, ni = R & 2047;
            size_t bhbase = ((size_t)(b * NH + h)) * ND * DH;
            float v0 = f2tf_f(acc[j][2 * hf + 0]);
            float v1 = f2tf_f(acc[j][2 * hf + 1]);
            if (which <= 1) {
                *(float2*)&C[bhbase + (size_t)ni * DH + col] = make_float2(v0, v1);
            } else if (which == 2) {
                C[bhbase + (size_t)ni * DH + ilc(col)]     = v0;
                C[bhbase + (size_t)ni * DH + ilc(col + 1)] = v1;
            } else {
                C[bhbase + (size_t)(ni >> 5) * 2048 + vadr(ni & 31, col)]     = v0;
                C[bhbase + (size_t)(ni >> 5) * 2048 + vadr(ni & 31, col + 1)] = v1;
            }
        }
    }
}

// ---------------------------------------------------------------------------
// Dual-softmax flash attention: register-resident S, cp.async double-buffered
// K/V tiles, LDS.64 fragment loads. CTA: 64 queries x 64-key tiles, 8 warps.
// Warps 0-3: stream1 (Q,O1); warps 4-7: stream2 (Q2,O2).
// ---------------------------------------------------------------------------
__global__ __launch_bounds__(256) void attn_mma_kernel()
{
    extern __shared__ float sm[];
    float* KsB = sm;               // 2 x KTILE
    float* VsB = sm + 2 * KTILE;   // 2 x VTILE

    int tid = threadIdx.x;
    int wid = tid >> 5, lane = tid & 31, grp = lane >> 2, qd = lane & 3;
    int half = wid >> 2;
    int wg   = wid & 3;
    int r0   = wg * 16;

    int bh = blockIdx.y, i0 = blockIdx.x * 64;
    const float* Qg = (half ? g_Q2 : g_Q) + ((size_t)bh * ND + i0) * DH;
    const float* Kg = g_K + (size_t)bh * ND * DH;
    const float* Vg = g_V + (size_t)bh * ND * DH;

    // Preload Q fragments (pre-rounded tf32 in gmem; *0.125 is exact)
    uint32_t qf[8][4];
    {
        const float* q0 = Qg + (size_t)(r0 + grp) * DH;
        const float* q1 = Qg + (size_t)(r0 + grp + 8) * DH;
        #pragma unroll
        for (int kk = 0; kk < 8; kk++) {
            qf[kk][0] = __float_as_uint(q0[kk * 8 + qd]     * 0.125f);
            qf[kk][1] = __float_as_uint(q1[kk * 8 + qd]     * 0.125f);
            qf[kk][2] = __float_as_uint(q0[kk * 8 + qd + 4] * 0.125f);
            qf[kk][3] = __float_as_uint(q1[kk * 8 + qd + 4] * 0.125f);
        }
    }

    float O[8][4] = {};
    float m_lo = -1e30f, m_hi = -1e30f, l_lo = 0.f, l_hi = 0.f;

    // cp.async tile loader: K tile = 1024 16B chunks, V tile = 1024 chunks.
    // 256 threads -> 4 K-chunks + 4 V-chunks per thread.
    auto issue_tile = [&](int kt, int buf) {
        const float* Kt = Kg + (size_t)kt * 64 * DH;
        const float* Vt = Vg + (size_t)kt * 64 * DH;
        float* Kd = KsB + buf * KTILE;
        float* Vd = VsB + buf * VTILE;
        #pragma unroll
        for (int i = 0; i < 4; i++) {
            int c = tid + 256 * i;              // 0..1023
            int n = c >> 4, w = (c & 15) << 2;  // row, word offset
            cpa16(&Kd[n * KP + w], &Kt[n * 64 + w]);
            int o = c << 2;                     // float offset 0..4092
            int blk = o >> 9, q = (o >> 7) & 3, wo = o & 127;
            cpa16(&Vd[blk * VBLK + q * VPN + wo], &Vt[o]);
        }
    };

    issue_tile(0, 0);
    asm volatile("cp.async.commit_group;");

    for (int kt = 0; kt < 32; kt++) {
        int cur = kt & 1;
        if (kt + 1 < 32) issue_tile(kt + 1, cur ^ 1);
        asm volatile("cp.async.commit_group;");
        asm volatile("cp.async.wait_group 1;");
        __syncthreads();

        const float* Ksb = KsB + cur * KTILE;
        const float* Vsb = VsB + cur * VTILE;

        // ---- S = (scaled Q) K^T, in registers ----
        float sacc[8][4] = {};
        #pragma unroll
        for (int kk = 0; kk < 8; kk++) {
            int kb = kk * 8;
            #pragma unroll
            for (int j = 0; j < 8; j++) {
                float2 bv = *(const float2*)&Ksb[(j * 8 + grp) * KP + kb + 2 * qd];
                uint32_t b[2] = { __float_as_uint(bv.x), __float_as_uint(bv.y) };
                mma8(sacc[j], qf[kk], b);
            }
        }

        // ---- register online softmax (quad-wide rows) ----
        {
            float mx_lo = -1e30f, mx_hi = -1e30f;
            #pragma unroll
            for (int j = 0; j < 8; j++) {
                mx_lo = fmaxf(mx_lo, fmaxf(sacc[j][0], sacc[j][1]));
                mx_hi = fmaxf(mx_hi, fmaxf(sacc[j][2], sacc[j][3]));
            }
            mx_lo = fmaxf(mx_lo, __shfl_xor_sync(0xffffffffu, mx_lo, 1));
            mx_lo = fmaxf(mx_lo, __shfl_xor_sync(0xffffffffu, mx_lo, 2));
            mx_hi = fmaxf(mx_hi, __shfl_xor_sync(0xffffffffu, mx_hi, 1));
            mx_hi = fmaxf(mx_hi, __shfl_xor_sync(0xffffffffu, mx_hi, 2));
            float mn_lo = fmaxf(m_lo, mx_lo), mn_hi = fmaxf(m_hi, mx_hi);
            float al_lo = __expf(m_lo - mn_lo), al_hi = __expf(m_hi - mn_hi);
            m_lo = mn_lo; m_hi = mn_hi;
            float s_lo = 0.f, s_hi = 0.f;
            #pragma unroll
            for (int j = 0; j < 8; j++) {
                sacc[j][0] = __expf(sacc[j][0] - mn_lo); s_lo += sacc[j][0];
                sacc[j][1] = __expf(sacc[j][1] - mn_lo); s_lo += sacc[j][1];
                sacc[j][2] = __expf(sacc[j][2] - mn_hi); s_hi += sacc[j][2];
                sacc[j][3] = __expf(sacc[j][3] - mn_hi); s_hi += sacc[j][3];
            }
            s_lo += __shfl_xor_sync(0xffffffffu, s_lo, 1);
            s_lo += __shfl_xor_sync(0xffffffffu, s_lo, 2);
            s_hi += __shfl_xor_sync(0xffffffffu, s_hi, 1);
            s_hi += __shfl_xor_sync(0xffffffffu, s_hi, 2);
            l_lo = l_lo * al_lo + s_lo;
            l_hi = l_hi * al_hi + s_hi;
            #pragma unroll
            for (int j = 0; j < 8; j++) {
                O[j][0] *= al_lo; O[j][1] *= al_lo;
                O[j][2] *= al_hi; O[j][3] *= al_hi;
            }
        }

        // ---- O += P V : transpose P (C-layout -> A-layout) via quad shuffles ----
        {
            int src  = qd >> 1;
            int src2 = src + 2;
            bool odd = qd & 1;
            #pragma unroll
            for (int kk = 0; kk < 8; kk++) {
                float x0 = __shfl_sync(0xffffffffu, sacc[kk][0], src, 4);
                float x1 = __shfl_sync(0xffffffffu, sacc[kk][1], src, 4);
                float x2 = __shfl_sync(0xffffffffu, sacc[kk][2], src, 4);
                float x3 = __shfl_sync(0xffffffffu, sacc[kk][3], src, 4);
                float y0 = __shfl_sync(0xffffffffu, sacc[kk][0], src2, 4);
                float y1 = __shfl_sync(0xffffffffu, sacc[kk][1], src2, 4);
                float y2 = __shfl_sync(0xffffffffu, sacc[kk][2], src2, 4);
                float y3 = __shfl_sync(0xffffffffu, sacc[kk][3], src2, 4);
                uint32_t a[4];
                a[0] = f2tf(odd ? x1 : x0);
                a[1] = f2tf(odd ? x3 : x2);
                a[2] = f2tf(odd ? y1 : y0);
                a[3] = f2tf(odd ? y3 : y2);
                #pragma unroll
                for (int j = 0; j < 8; j++) {
                    float2 v = *(const float2*)&Vsb[kk * VBLK + qd * VPN + 2 * (j * 8 + grp)];
                    uint32_t b[2] = { __float_as_uint(v.x), __float_as_uint(v.y) };
                    mma8(O[j], a, b);
                }
            }
        }
        __syncthreads();
    }

    // ---- epilogue: out = 0.3*O1/l1 + 0.7*O2/l2, staged through KsB ----
    if (half == 0) {
        float s_lo = 0.3f / l_lo, s_hi = 0.3f / l_hi;
        #pragma unroll
        for (int j = 0; j < 8; j++) {
            int col = j * 8 + 2 * qd;
            *(float2*)&KsB[(r0 + grp) * KP + col] =
                make_float2(O[j][0] * s_lo, O[j][1] * s_lo);
            *(float2*)&KsB[(r0 + grp + 8) * KP + col] =
                make_float2(O[j][2] * s_hi, O[j][3] * s_hi);
        }
    }
    __syncthreads();
    if (half == 1) {
        float s_lo = 0.7f / l_lo, s_hi = 0.7f / l_hi;
        int b = bh >> 2, h = bh & 3;
        float* outp = g_Ao + ((size_t)b * ND + i0) * INNER + h * DH;
        #pragma unroll
        for (int j = 0; j < 8; j++) {
            int col = j * 8 + 2 * qd;
            float2 p = *(float2*)&KsB[(r0 + grp) * KP + col];
            *(float2*)&outp[(size_t)(r0 + grp) * INNER + col] =
                make_float2(p.x + O[j][0] * s_lo, p.y + O[j][1] * s_lo);
            p = *(float2*)&KsB[(r0 + grp + 8) * KP + col];
            *(float2*)&outp[(size_t)(r0 + grp + 8) * INNER + col] =
                make_float2(p.x + O[j][2] * s_hi, p.y + O[j][3] * s_hi);
        }
    }
}

// ---------------------------------------------------------------------------
// Output projection (tf32 MMA): out = Ao[8192,256] @ Wo[256,512] + bo
// ---------------------------------------------------------------------------
__global__ __launch_bounds__(256) void outproj_mma_kernel(
    const float* __restrict__ Wo, const float* __restrict__ bo,
    float* __restrict__ out)
{
    extern __shared__ float sm[];
    float* As = sm;
    float* Ws = sm + 128 * AP;

    int tid  = threadIdx.x;
    int wid  = tid >> 5, lane = tid & 31, grp = lane >> 2, qd = lane & 3;
    int row0 = blockIdx.x * 128;
    int col0 = blockIdx.y * 64;
    int r0   = wid * 16;

    float acc[8][4] = {};

    for (int k0 = 0; k0 < INNER; k0 += 64) {
        for (int i = tid; i < 128 * 16; i += 256) {
            int r = i >> 4, c4 = (i & 15) << 2;
            float4 v = *(const float4*)&g_Ao[(size_t)(row0 + r) * INNER + k0 + c4];
            int base = r * AP + (c4 & ~7) + ((c4 & 4) ? 1 : 0);
            As[base + 0] = f2tf_f(v.x);
            As[base + 2] = f2tf_f(v.y);
            As[base + 4] = f2tf_f(v.z);
            As[base + 6] = f2tf_f(v.w);
        }
        for (int i = tid; i < 64 * 16; i += 256) {
            int r = i >> 4, c4 = (i & 15) << 2;
            float4 v = *(const float4*)&Wo[(size_t)(k0 + r) * QD + col0 + c4];
            int base = (r >> 3) * VBLK + (r & 3) * VPN + ((r >> 2) & 1) + 2 * c4;
            Ws[base + 0] = f2tf_f(v.x);
            Ws[base + 2] = f2tf_f(v.y);
            Ws[base + 4] = f2tf_f(v.z);
            Ws[base + 6] = f2tf_f(v.w);
        }
        __syncthreads();
        #pragma unroll
        for (int kk = 0; kk < 8; kk++) {
            int kb = kk * 8;
            float2 alo = *(const float2*)&As[(r0 + grp) * AP + kb + 2 * qd];
            float2 ahi = *(const float2*)&As[(r0 + grp + 8) * AP + kb + 2 * qd];
            uint32_t a[4];
            a[0] = __float_as_uint(alo.x); a[1] = __float_as_uint(ahi.x);
            a[2] = __float_as_uint(alo.y); a[3] = __float_as_uint(ahi.y);
            #pragma unroll
            for (int j = 0; j < 8; j++) {
                float2 bv = *(const float2*)&Ws[kk * VBLK + qd * VPN + 2 * (j * 8 + grp)];
                uint32_t b[2] = { __float_as_uint(bv.x), __float_as_uint(bv.y) };
                mma8(acc[j], a, b);
            }
        }
        __syncthreads();
    }

    #pragma unroll
    for (int j = 0; j < 8; j++) {
        int col = j * 8 + 2 * qd;
        float b0 = bo[col0 + col], b1 = bo[col0 + col + 1];
        int R = row0 + r0 + grp;
        *(float2*)&out[(size_t)R * QD + col0 + col] =
            make_float2(acc[j][0] + b0, acc[j][1] + b1);
        R += 8;
        *(float2*)&out[(size_t)R * QD + col0 + col] =
            make_float2(acc[j][2] + b0, acc[j][3] + b1);
    }
}

// ---------------------------------------------------------------------------
extern "C" void kernel_launch(void* const* d_in, const int* in_sizes, int n_in,
                              void* d_out, int out_size)
{
    const float* x1  = (const float*)d_in[0];
    const float* x2  = (const float*)d_in[1];
    const float* ctx = (const float*)d_in[2];
    const float* Wq  = (const float*)d_in[3];
    const float* Wq2 = (const float*)d_in[4];
    const float* Wk  = (const float*)d_in[5];
    const float* Wv  = (const float*)d_in[6];
    const float* Wo  = (const float*)d_in[7];
    const float* bo  = (const float*)d_in[8];
    float* out = (float*)d_out;

    const int gemm_smem = (128 * AP + VTILE) * sizeof(float);       // ~53 KB
    const int attn_smem = 2 * (KTILE + VTILE) * sizeof(float);      // 71.7 KB

    // Unconditional (no static guards); idempotent host-side calls.
    cudaFuncSetAttribute(proj_mma_kernel,
        cudaFuncAttributeMaxDynamicSharedMemorySize, gemm_smem);
    cudaFuncSetAttribute(attn_mma_kernel,
        cudaFuncAttributeMaxDynamicSharedMemorySize, attn_smem);
    cudaFuncSetAttribute(outproj_mma_kernel,
        cudaFuncAttributeMaxDynamicSharedMemorySize, gemm_smem);

    // 1) projections: Q, Q2, K, V (tf32 MMA; K/V in attention-ready layouts)
    proj_mma_kernel<<<dim3(64, 4, 4), 256, gemm_smem>>>(x1, x2, ctx, Wq, Wq2, Wk, Wv);

    // 2) dual-softmax flash attention (cp.async double-buffered, tf32 MMA)
    attn_mma_kernel<<<dim3(32, 16), 256, attn_smem>>>();

    // 3) output projection + bias (tf32 MMA)
    outproj_mma_kernel<<<dim3(64, 8), 256, attn_smem > gemm_smem ? gemm_smem : gemm_smem>>>(Wo, bo, out);
}

// round 14
// speedup vs baseline: 3.5154x; 1.0327x over previous
#include <cuda_runtime.h>
#include <cstdint>

#define NB 4
#define NH 4
#define DH 64
#define ND 2048
#define QD 512
#define INNER 256

// attention smem pitches (all chosen so pitch mod 32 == 8 for conflict-free LDS.64)
#define KP   72          // K tile row pitch (words)
#define VPN  136         // V/W blocked layout: per-q-row pitch
#define VBLK 544         // V/W blocked layout: per-8k-block pitch (4*VPN)
#define KTILE (64*KP)    // 4608 words
#define VTILE (8*VBLK)   // 4352 words
#define AP   72          // GEMM As pitch (== KP, reused for staging epilogues)

// Scratch (allocation-free: __device__ globals)
__device__ float g_Q [NB*NH*ND*DH];
__device__ float g_Q2[NB*NH*ND*DH];
__device__ float g_K [NB*NH*ND*DH];   // pair-interleaved columns, tf32-rounded
__device__ float g_V [NB*NH*ND*DH];   // row-pair-blocked layout, tf32-rounded
__device__ float g_Ao[NB*ND*INNER];

// ---------------------------------------------------------------------------
__device__ __forceinline__ uint32_t f2tf(float x) {
    uint32_t r; asm("cvt.rna.tf32.f32 %0, %1;" : "=r"(r) : "f"(x)); return r;
}
__device__ __forceinline__ float f2tf_f(float x) { return __uint_as_float(f2tf(x)); }

// pair-interleave within 8-wide blocks: d -> (d&~7) + 2*(d&3) + ((d>>2)&1)
__device__ __forceinline__ int ilc(int d) {
    return (d & ~7) + 2 * (d & 3) + ((d >> 2) & 1);
}

__device__ __forceinline__ void mma8(float* c, const uint32_t* a, const uint32_t* b) {
    asm volatile(
        "mma.sync.aligned.m16n8k8.row.col.f32.tf32.tf32.f32 "
        "{%0,%1,%2,%3}, {%4,%5,%6,%7}, {%8,%9}, {%0,%1,%2,%3};\n"
        : "+f"(c[0]), "+f"(c[1]), "+f"(c[2]), "+f"(c[3])
        : "r"(a[0]), "r"(a[1]), "r"(a[2]), "r"(a[3]), "r"(b[0]), "r"(b[1]));
}

__device__ __forceinline__ void cpa16(float* dst, const float* src) {
    uint32_t d = (uint32_t)__cvta_generic_to_shared(dst);
    asm volatile("cp.async.cg.shared.global [%0], [%1], 16;" :: "r"(d), "l"(src));
}

// ---------------------------------------------------------------------------
// Projection GEMM (tf32 MMA, register double-buffered loads):
// C = A[8192,512] @ W[512,256], head-split, tf32-pre-rounded outputs;
// K/V written in attention-ready layouts via smem-staged coalesced epilogue.
// CTA tile: 128 rows x 64 cols. 8 warps.
// ---------------------------------------------------------------------------
__global__ __launch_bounds__(256) void proj_mma_kernel(
    const float* __restrict__ x1, const float* __restrict__ x2,
    const float* __restrict__ ctx,
    const float* __restrict__ Wq, const float* __restrict__ Wq2,
    const float* __restrict__ Wk, const float* __restrict__ Wv)
{
    extern __shared__ float sm[];
    float* As = sm;             // 128 x AP (9216 w) — also epilogue staging
    float* Ws = sm + 128 * AP;  // blocked k-row layout (VTILE w)

    const float* A; const float* W; float* C;
    int which = blockIdx.z;
    if      (which == 0) { A = x1;  W = Wq;  C = g_Q;  }
    else if (which == 1) { A = x2;  W = Wq2; C = g_Q2; }
    else if (which == 2) { A = ctx; W = Wk;  C = g_K;  }
    else                 { A = ctx; W = Wv;  C = g_V;  }

    int tid  = threadIdx.x;
    int wid  = tid >> 5, lane = tid & 31, grp = lane >> 2, qd = lane & 3;
    int row0 = blockIdx.x * 128;
    int col0 = blockIdx.y * 64;
    int r0   = wid * 16;

    float4 bufA[8], bufW[4];
    #pragma unroll
    for (int ii = 0; ii < 8; ii++) {
        int i = tid + 256 * ii, r = i >> 4, c4 = (i & 15) << 2;
        bufA[ii] = *(const float4*)&A[(size_t)(row0 + r) * QD + c4];
    }
    #pragma unroll
    for (int ii = 0; ii < 4; ii++) {
        int i = tid + 256 * ii, r = i >> 4, c4 = (i & 15) << 2;
        bufW[ii] = *(const float4*)&W[(size_t)r * INNER + col0 + c4];
    }

    float acc[8][4] = {};

    for (int k0 = 0; k0 < QD; k0 += 64) {
        #pragma unroll
        for (int ii = 0; ii < 8; ii++) {
            int i = tid + 256 * ii, r = i >> 4, c4 = (i & 15) << 2;
            int base = r * AP + (c4 & ~7) + ((c4 & 4) ? 1 : 0);
            As[base + 0] = f2tf_f(bufA[ii].x);
            As[base + 2] = f2tf_f(bufA[ii].y);
            As[base + 4] = f2tf_f(bufA[ii].z);
            As[base + 6] = f2tf_f(bufA[ii].w);
        }
        #pragma unroll
        for (int ii = 0; ii < 4; ii++) {
            int i = tid + 256 * ii, r = i >> 4, c4 = (i & 15) << 2;
            int base = (r >> 3) * VBLK + (r & 3) * VPN + ((r >> 2) & 1) + 2 * c4;
            Ws[base + 0] = f2tf_f(bufW[ii].x);
            Ws[base + 2] = f2tf_f(bufW[ii].y);
            Ws[base + 4] = f2tf_f(bufW[ii].z);
            Ws[base + 6] = f2tf_f(bufW[ii].w);
        }
        __syncthreads();

        if (k0 + 64 < QD) {   // prefetch next k-block (overlaps mma below)
            #pragma unroll
            for (int ii = 0; ii < 8; ii++) {
                int i = tid + 256 * ii, r = i >> 4, c4 = (i & 15) << 2;
                bufA[ii] = *(const float4*)&A[(size_t)(row0 + r) * QD + k0 + 64 + c4];
            }
            #pragma unroll
            for (int ii = 0; ii < 4; ii++) {
                int i = tid + 256 * ii, r = i >> 4, c4 = (i & 15) << 2;
                bufW[ii] = *(const float4*)&W[(size_t)(k0 + 64 + r) * INNER + col0 + c4];
            }
        }

        #pragma unroll
        for (int kk = 0; kk < 8; kk++) {
            int kb = kk * 8;
            float2 alo = *(const float2*)&As[(r0 + grp) * AP + kb + 2 * qd];
            float2 ahi = *(const float2*)&As[(r0 + grp + 8) * AP + kb + 2 * qd];
            uint32_t a[4];
            a[0] = __float_as_uint(alo.x); a[1] = __float_as_uint(ahi.x);
            a[2] = __float_as_uint(alo.y); a[3] = __float_as_uint(ahi.y);
            #pragma unroll
            for (int j = 0; j < 8; j++) {
                float2 bv = *(const float2*)&Ws[kk * VBLK + qd * VPN + 2 * (j * 8 + grp)];
                uint32_t b[2] = { __float_as_uint(bv.x), __float_as_uint(bv.y) };
                mma8(acc[j], a, b);
            }
        }
        __syncthreads();
    }

    int h = blockIdx.y;
    if (which <= 1) {
        // Q / Q2: direct float2 stores (plain row layout)
        #pragma unroll
        for (int j = 0; j < 8; j++) {
            int col = j * 8 + 2 * qd;
            #pragma unroll
            for (int hf = 0; hf < 2; hf++) {
                int R = row0 + r0 + grp + hf * 8;
                int b = R >> 11, ni = R & 2047;
                *(float2*)&C[(((size_t)(b * NH + h)) * ND + ni) * DH + col] =
                    make_float2(f2tf_f(acc[j][2 * hf + 0]), f2tf_f(acc[j][2 * hf + 1]));
            }
        }
    } else {
        // K / V: stage interleaved layout into As (padded), then coalesced copy-out
        #pragma unroll
        for (int j = 0; j < 8; j++) {
            int col = j * 8 + 2 * qd;
            #pragma unroll
            for (int hf = 0; hf < 2; hf++) {
                int m = r0 + grp + hf * 8;       // local row 0..127
                float v0 = f2tf_f(acc[j][2 * hf + 0]);
                float v1 = f2tf_f(acc[j][2 * hf + 1]);
                if (which == 2) {
                    As[m * AP + ilc(col)]     = v0;
                    As[m * AP + ilc(col + 1)] = v1;
                } else {
                    int base = (m >> 3) * VBLK + (m & 3) * VPN + ((m >> 2) & 1);
                    As[base + 2 * col]       = v0;
                    As[base + 2 * (col + 1)] = v1;
                }
            }
        }
        __syncthreads();
        int b  = row0 >> 11;
        int nb = row0 & 2047;
        float* dst = C + ((size_t)(b * NH + h)) * ND * DH + (size_t)nb * DH;
        if (which == 2) {
            #pragma unroll
            for (int ii = 0; ii < 8; ii++) {
                int o = (tid + 256 * ii) << 2;            // 0..8188
                int m = o >> 6, w = o & 63;
                *(float4*)&dst[o] = *(const float4*)&As[m * AP + w];
            }
        } else {
            #pragma unroll
            for (int ii = 0; ii < 8; ii++) {
                int o = (tid + 256 * ii) << 2;
                int blk = o >> 9, q = (o >> 7) & 3, w = o & 127;
                *(float4*)&dst[o] = *(const float4*)&As[blk * VBLK + q * VPN + w];
            }
        }
    }
}

// ---------------------------------------------------------------------------
// Dual-softmax flash attention: register-resident S, cp.async double-buffered
// K/V tiles, LDS.64 fragment loads. CTA: 64 queries x 64-key tiles, 8 warps.
// Warps 0-3: stream1 (Q,O1); warps 4-7: stream2 (Q2,O2).
// ---------------------------------------------------------------------------
__global__ __launch_bounds__(256) void attn_mma_kernel()
{
    extern __shared__ float sm[];
    float* KsB = sm;               // 2 x KTILE
    float* VsB = sm + 2 * KTILE;   // 2 x VTILE

    int tid = threadIdx.x;
    int wid = tid >> 5, lane = tid & 31, grp = lane >> 2, qd = lane & 3;
    int half = wid >> 2;
    int wg   = wid & 3;
    int r0   = wg * 16;

    int bh = blockIdx.y, i0 = blockIdx.x * 64;
    const float* Qg = (half ? g_Q2 : g_Q) + ((size_t)bh * ND + i0) * DH;
    const float* Kg = g_K + (size_t)bh * ND * DH;
    const float* Vg = g_V + (size_t)bh * ND * DH;

    // Preload Q fragments (pre-rounded tf32 in gmem; *0.125 is exact)
    uint32_t qf[8][4];
    {
        const float* q0 = Qg + (size_t)(r0 + grp) * DH;
        const float* q1 = Qg + (size_t)(r0 + grp + 8) * DH;
        #pragma unroll
        for (int kk = 0; kk < 8; kk++) {
            qf[kk][0] = __float_as_uint(q0[kk * 8 + qd]     * 0.125f);
            qf[kk][1] = __float_as_uint(q1[kk * 8 + qd]     * 0.125f);
            qf[kk][2] = __float_as_uint(q0[kk * 8 + qd + 4] * 0.125f);
            qf[kk][3] = __float_as_uint(q1[kk * 8 + qd + 4] * 0.125f);
        }
    }

    float O[8][4] = {};
    float m_lo = -1e30f, m_hi = -1e30f, l_lo = 0.f, l_hi = 0.f;

    // cp.async tile loader: K tile = 1024 16B chunks, V tile = 1024 chunks.
    auto issue_tile = [&](int kt, int buf) {
        const float* Kt = Kg + (size_t)kt * 64 * DH;
        const float* Vt = Vg + (size_t)kt * 64 * DH;
        float* Kd = KsB + buf * KTILE;
        float* Vd = VsB + buf * VTILE;
        #pragma unroll
        for (int i = 0; i < 4; i++) {
            int c = tid + 256 * i;              // 0..1023
            int n = c >> 4, w = (c & 15) << 2;  // row, word offset
            cpa16(&Kd[n * KP + w], &Kt[n * 64 + w]);
            int o = c << 2;                     // float offset 0..4092
            int blk = o >> 9, q = (o >> 7) & 3, wo = o & 127;
            cpa16(&Vd[blk * VBLK + q * VPN + wo], &Vt[o]);
        }
    };

    issue_tile(0, 0);
    asm volatile("cp.async.commit_group;");

    for (int kt = 0; kt < 32; kt++) {
        int cur = kt & 1;
        if (kt + 1 < 32) issue_tile(kt + 1, cur ^ 1);
        asm volatile("cp.async.commit_group;");
        asm volatile("cp.async.wait_group 1;");
        __syncthreads();

        const float* Ksb = KsB + cur * KTILE;
        const float* Vsb = VsB + cur * VTILE;

        // ---- S = (scaled Q) K^T, in registers ----
        float sacc[8][4] = {};
        #pragma unroll
        for (int kk = 0; kk < 8; kk++) {
            int kb = kk * 8;
            #pragma unroll
            for (int j = 0; j < 8; j++) {
                float2 bv = *(const float2*)&Ksb[(j * 8 + grp) * KP + kb + 2 * qd];
                uint32_t b[2] = { __float_as_uint(bv.x), __float_as_uint(bv.y) };
                mma8(sacc[j], qf[kk], b);
            }
        }

        // ---- register online softmax (quad-wide rows) ----
        {
            float mx_lo = -1e30f, mx_hi = -1e30f;
            #pragma unroll
            for (int j = 0; j < 8; j++) {
                mx_lo = fmaxf(mx_lo, fmaxf(sacc[j][0], sacc[j][1]));
                mx_hi = fmaxf(mx_hi, fmaxf(sacc[j][2], sacc[j][3]));
            }
            mx_lo = fmaxf(mx_lo, __shfl_xor_sync(0xffffffffu, mx_lo, 1));
            mx_lo = fmaxf(mx_lo, __shfl_xor_sync(0xffffffffu, mx_lo, 2));
            mx_hi = fmaxf(mx_hi, __shfl_xor_sync(0xffffffffu, mx_hi, 1));
            mx_hi = fmaxf(mx_hi, __shfl_xor_sync(0xffffffffu, mx_hi, 2));
            float mn_lo = fmaxf(m_lo, mx_lo), mn_hi = fmaxf(m_hi, mx_hi);
            float al_lo = __expf(m_lo - mn_lo), al_hi = __expf(m_hi - mn_hi);
            m_lo = mn_lo; m_hi = mn_hi;
            float s_lo = 0.f, s_hi = 0.f;
            #pragma unroll
            for (int j = 0; j < 8; j++) {
                sacc[j][0] = __expf(sacc[j][0] - mn_lo); s_lo += sacc[j][0];
                sacc[j][1] = __expf(sacc[j][1] - mn_lo); s_lo += sacc[j][1];
                sacc[j][2] = __expf(sacc[j][2] - mn_hi); s_hi += sacc[j][2];
                sacc[j][3] = __expf(sacc[j][3] - mn_hi); s_hi += sacc[j][3];
            }
            s_lo += __shfl_xor_sync(0xffffffffu, s_lo, 1);
            s_lo += __shfl_xor_sync(0xffffffffu, s_lo, 2);
            s_hi += __shfl_xor_sync(0xffffffffu, s_hi, 1);
            s_hi += __shfl_xor_sync(0xffffffffu, s_hi, 2);
            l_lo = l_lo * al_lo + s_lo;
            l_hi = l_hi * al_hi + s_hi;
            #pragma unroll
            for (int j = 0; j < 8; j++) {
                O[j][0] *= al_lo; O[j][1] *= al_lo;
                O[j][2] *= al_hi; O[j][3] *= al_hi;
            }
        }

        // ---- O += P V : transpose P (C-layout -> A-layout) via quad shuffles ----
        {
            int src  = qd >> 1;
            int src2 = src + 2;
            bool odd = qd & 1;
            #pragma unroll
            for (int kk = 0; kk < 8; kk++) {
                float x0 = __shfl_sync(0xffffffffu, sacc[kk][0], src, 4);
                float x1 = __shfl_sync(0xffffffffu, sacc[kk][1], src, 4);
                float x2 = __shfl_sync(0xffffffffu, sacc[kk][2], src, 4);
                float x3 = __shfl_sync(0xffffffffu, sacc[kk][3], src, 4);
                float y0 = __shfl_sync(0xffffffffu, sacc[kk][0], src2, 4);
                float y1 = __shfl_sync(0xffffffffu, sacc[kk][1], src2, 4);
                float y2 = __shfl_sync(0xffffffffu, sacc[kk][2], src2, 4);
                float y3 = __shfl_sync(0xffffffffu, sacc[kk][3], src2, 4);
                uint32_t a[4];
                a[0] = f2tf(odd ? x1 : x0);
                a[1] = f2tf(odd ? x3 : x2);
                a[2] = f2tf(odd ? y1 : y0);
                a[3] = f2tf(odd ? y3 : y2);
                #pragma unroll
                for (int j = 0; j < 8; j++) {
                    float2 v = *(const float2*)&Vsb[kk * VBLK + qd * VPN + 2 * (j * 8 + grp)];
                    uint32_t b[2] = { __float_as_uint(v.x), __float_as_uint(v.y) };
                    mma8(O[j], a, b);
                }
            }
        }
        __syncthreads();
    }

    // ---- epilogue: out = 0.3*O1/l1 + 0.7*O2/l2, staged through KsB ----
    if (half == 0) {
        float s_lo = 0.3f / l_lo, s_hi = 0.3f / l_hi;
        #pragma unroll
        for (int j = 0; j < 8; j++) {
            int col = j * 8 + 2 * qd;
            *(float2*)&KsB[(r0 + grp) * KP + col] =
                make_float2(O[j][0] * s_lo, O[j][1] * s_lo);
            *(float2*)&KsB[(r0 + grp + 8) * KP + col] =
                make_float2(O[j][2] * s_hi, O[j][3] * s_hi);
        }
    }
    __syncthreads();
    if (half == 1) {
        float s_lo = 0.7f / l_lo, s_hi = 0.7f / l_hi;
        int b = bh >> 2, h = bh & 3;
        float* outp = g_Ao + ((size_t)b * ND + i0) * INNER + h * DH;
        #pragma unroll
        for (int j = 0; j < 8; j++) {
            int col = j * 8 + 2 * qd;
            float2 p = *(float2*)&KsB[(r0 + grp) * KP + col];
            *(float2*)&outp[(size_t)(r0 + grp) * INNER + col] =
                make_float2(p.x + O[j][0] * s_lo, p.y + O[j][1] * s_lo);
            p = *(float2*)&KsB[(r0 + grp + 8) * KP + col];
            *(float2*)&outp[(size_t)(r0 + grp + 8) * INNER + col] =
                make_float2(p.x + O[j][2] * s_hi, p.y + O[j][3] * s_hi);
        }
    }
}

// ---------------------------------------------------------------------------
// Output projection (tf32 MMA, register double-buffered loads):
// out = Ao[8192,256] @ Wo[256,512] + bo
// ---------------------------------------------------------------------------
__global__ __launch_bounds__(256) void outproj_mma_kernel(
    const float* __restrict__ Wo, const float* __restrict__ bo,
    float* __restrict__ out)
{
    extern __shared__ float sm[];
    float* As = sm;
    float* Ws = sm + 128 * AP;

    int tid  = threadIdx.x;
    int wid  = tid >> 5, lane = tid & 31, grp = lane >> 2, qd = lane & 3;
    int row0 = blockIdx.x * 128;
    int col0 = blockIdx.y * 64;
    int r0   = wid * 16;

    float4 bufA[8], bufW[4];
    #pragma unroll
    for (int ii = 0; ii < 8; ii++) {
        int i = tid + 256 * ii, r = i >> 4, c4 = (i & 15) << 2;
        bufA[ii] = *(const float4*)&g_Ao[(size_t)(row0 + r) * INNER + c4];
    }
    #pragma unroll
    for (int ii = 0; ii < 4; ii++) {
        int i = tid + 256 * ii, r = i >> 4, c4 = (i & 15) << 2;
        bufW[ii] = *(const float4*)&Wo[(size_t)r * QD + col0 + c4];
    }

    float acc[8][4] = {};

    for (int k0 = 0; k0 < INNER; k0 += 64) {
        #pragma unroll
        for (int ii = 0; ii < 8; ii++) {
            int i = tid + 256 * ii, r = i >> 4, c4 = (i & 15) << 2;
            int base = r * AP + (c4 & ~7) + ((c4 & 4) ? 1 : 0);
            As[base + 0] = f2tf_f(bufA[ii].x);
            As[base + 2] = f2tf_f(bufA[ii].y);
            As[base + 4] = f2tf_f(bufA[ii].z);
            As[base + 6] = f2tf_f(bufA[ii].w);
        }
        #pragma unroll
        for (int ii = 0; ii < 4; ii++) {
            int i = tid + 256 * ii, r = i >> 4, c4 = (i & 15) << 2;
            int base = (r >> 3) * VBLK + (r & 3) * VPN + ((r >> 2) & 1) + 2 * c4;
            Ws[base + 0] = f2tf_f(bufW[ii].x);
            Ws[base + 2] = f2tf_f(bufW[ii].y);
            Ws[base + 4] = f2tf_f(bufW[ii].z);
            Ws[base + 6] = f2tf_f(bufW[ii].w);
        }
        __syncthreads();

        if (k0 + 64 < INNER) {
            #pragma unroll
            for (int ii = 0; ii < 8; ii++) {
                int i = tid + 256 * ii, r = i >> 4, c4 = (i & 15) << 2;
                bufA[ii] = *(const float4*)&g_Ao[(size_t)(row0 + r) * INNER + k0 + 64 + c4];
            }
            #pragma unroll
            for (int ii = 0; ii < 4; ii++) {
                int i = tid + 256 * ii, r = i >> 4, c4 = (i & 15) << 2;
                bufW[ii] = *(const float4*)&Wo[(size_t)(k0 + 64 + r) * QD + col0 + c4];
            }
        }

        #pragma unroll
        for (int kk = 0; kk < 8; kk++) {
            int kb = kk * 8;
            float2 alo = *(const float2*)&As[(r0 + grp) * AP + kb + 2 * qd];
            float2 ahi = *(const float2*)&As[(r0 + grp + 8) * AP + kb + 2 * qd];
            uint32_t a[4];
            a[0] = __float_as_uint(alo.x); a[1] = __float_as_uint(ahi.x);
            a[2] = __float_as_uint(alo.y); a[3] = __float_as_uint(ahi.y);
            #pragma unroll
            for (int j = 0; j < 8; j++) {
                float2 bv = *(const float2*)&Ws[kk * VBLK + qd * VPN + 2 * (j * 8 + grp)];
                uint32_t b[2] = { __float_as_uint(bv.x), __float_as_uint(bv.y) };
                mma8(acc[j], a, b);
            }
        }
        __syncthreads();
    }

    #pragma unroll
    for (int j = 0; j < 8; j++) {
        int col = j * 8 + 2 * qd;
        float b0 = bo[col0 + col], b1 = bo[col0 + col + 1];
        int R = row0 + r0 + grp;
        *(float2*)&out[(size_t)R * QD + col0 + col] =
            make_float2(acc[j][0] + b0, acc[j][1] + b1);
        R += 8;
        *(float2*)&out[(size_t)R * QD + col0 + col] =
            make_float2(acc[j][2] + b0, acc[j][3] + b1);
    }
}

// ---------------------------------------------------------------------------
extern "C" void kernel_launch(void* const* d_in, const int* in_sizes, int n_in,
                              void* d_out, int out_size)
{
    const float* x1  = (const float*)d_in[0];
    const float* x2  = (const float*)d_in[1];
    const float* ctx = (const float*)d_in[2];
    const float* Wq  = (const float*)d_in[3];
    const float* Wq2 = (const float*)d_in[4];
    const float* Wk  = (const float*)d_in[5];
    const float* Wv  = (const float*)d_in[6];
    const float* Wo  = (const float*)d_in[7];
    const float* bo  = (const float*)d_in[8];
    float* out = (float*)d_out;

    const int gemm_smem = (128 * AP + VTILE) * sizeof(float);       // ~53 KB
    const int attn_smem = 2 * (KTILE + VTILE) * sizeof(float);      // 71.7 KB

    // Unconditional (no static guards); idempotent host-side calls.
    cudaFuncSetAttribute(proj_mma_kernel,
        cudaFuncAttributeMaxDynamicSharedMemorySize, gemm_smem);
    cudaFuncSetAttribute(attn_mma_kernel,
        cudaFuncAttributeMaxDynamicSharedMemorySize, attn_smem);
    cudaFuncSetAttribute(outproj_mma_kernel,
        cudaFuncAttributeMaxDynamicSharedMemorySize, gemm_smem);

    // 1) projections: Q, Q2, K, V (tf32 MMA; K/V in attention-ready layouts)
    proj_mma_kernel<<<dim3(64, 4, 4), 256, gemm_smem>>>(x1, x2, ctx, Wq, Wq2, Wk, Wv);

    // 2) dual-softmax flash attention (cp.async double-buffered, tf32 MMA)
    attn_mma_kernel<<<dim3(32, 16), 256, attn_smem>>>();

    // 3) output projection + bias (tf32 MMA)
    outproj_mma_kernel<<<dim3(64, 8), 256, gemm_smem>>>(Wo, bo, out);
}

// round 15
// speedup vs baseline: 4.3270x; 1.2309x over previous
#include <cuda_runtime.h>
#include <cstdint>

#define NB 4
#define NH 4
#define DH 64
#define ND 2048
#define QD 512
#define INNER 256

// attention smem pitches (pitch mod 32 == 8 -> conflict-free LDS.64)
#define KP   72          // K tile row pitch (words)
#define VPN  136         // blocked layout: per-qd-row pitch
#define VBLK 544         // blocked layout: per-8k-block pitch (4*VPN)
#define KTILE (64*KP)    // 4608 words
#define VTILE (8*VBLK)   // 4352 words
#define PRA  68          // raw A-tile pitch (banks 4*grp+qd -> conflict-free scalar)

// Scratch (allocation-free: __device__ globals)
__device__ float g_Q [NB*NH*ND*DH];
__device__ float g_Q2[NB*NH*ND*DH];
__device__ float g_K [NB*NH*ND*DH];   // pair-interleaved columns, tf32-rounded
__device__ float g_V [NB*NH*ND*DH];   // row-pair-blocked layout, tf32-rounded
__device__ float g_Ao[NB*ND*INNER];
__device__ float g_W [4*4*8*4096];    // 4 projs x 4 col-tiles x 8 k-blocks x (64x64 blocked)
__device__ float g_Wo[8*4*4096];      // 8 col-tiles x 4 k-blocks x (64x64 blocked)

// ---------------------------------------------------------------------------
__device__ __forceinline__ uint32_t f2tf(float x) {
    uint32_t r; asm("cvt.rna.tf32.f32 %0, %1;" : "=r"(r) : "f"(x)); return r;
}
__device__ __forceinline__ float f2tf_f(float x) { return __uint_as_float(f2tf(x)); }

// pair-interleave within 8-wide blocks: d -> (d&~7) + 2*(d&3) + ((d>>2)&1)
__device__ __forceinline__ int ilc(int d) {
    return (d & ~7) + 2 * (d & 3) + ((d >> 2) & 1);
}

__device__ __forceinline__ void mma8(float* c, const uint32_t* a, const uint32_t* b) {
    asm volatile(
        "mma.sync.aligned.m16n8k8.row.col.f32.tf32.tf32.f32 "
        "{%0,%1,%2,%3}, {%4,%5,%6,%7}, {%8,%9}, {%0,%1,%2,%3};\n"
        : "+f"(c[0]), "+f"(c[1]), "+f"(c[2]), "+f"(c[3])
        : "r"(a[0]), "r"(a[1]), "r"(a[2]), "r"(a[3]), "r"(b[0]), "r"(b[1]));
}

__device__ __forceinline__ void cpa16(float* dst, const float* src) {
    uint32_t d = (uint32_t)__cvta_generic_to_shared(dst);
    asm volatile("cp.async.cg.shared.global [%0], [%1], 16;" :: "r"(d), "l"(src));
}

// ---------------------------------------------------------------------------
// Weight prep: tf32-round + block-layout all weights (runs every launch).
// Blocked 64x64 tile layout: idx = koct*512 + qd*128 + 2*ncol + hi
// for k-local kl: koct=kl>>3, qd=kl&3, hi=(kl>>2)&1.
// ---------------------------------------------------------------------------
__global__ __launch_bounds__(256) void prep_w_kernel(
    const float* __restrict__ Wq, const float* __restrict__ Wq2,
    const float* __restrict__ Wk, const float* __restrict__ Wv,
    const float* __restrict__ Wo)
{
    int idx = blockIdx.x * 256 + threadIdx.x;
    if (idx < 4 * QD * INNER) {
        int p = idx >> 17, rem = idx & 131071;
        int k = rem >> 8, c = rem & 255;
        const float* W = (p == 0) ? Wq : (p == 1) ? Wq2 : (p == 2) ? Wk : Wv;
        float v = W[k * INNER + c];
        int t = c >> 6, kb = k >> 6, kl = k & 63, nc = c & 63;
        g_W[(((p * 4 + t) * 8 + kb) << 12) + ((kl >> 3) << 9) + ((kl & 3) << 7)
            + 2 * nc + ((kl >> 2) & 1)] = f2tf_f(v);
    } else {
        int r = idx - 4 * QD * INNER;   // 0..131071
        int k = r >> 9, c = r & 511;
        float v = Wo[k * QD + c];
        int t = c >> 6, kb = k >> 6, kl = k & 63, nc = c & 63;
        g_Wo[(((t * 4 + kb)) << 12) + ((kl >> 3) << 9) + ((kl & 3) << 7)
             + 2 * nc + ((kl >> 2) & 1)] = f2tf_f(v);
    }
}

// ---------------------------------------------------------------------------
// Projection GEMM (tf32 MMA, cp.async double-buffered):
// C = A[8192,512] @ W[512,256], head-split, tf32-pre-rounded outputs;
// K/V written in attention-ready layouts via smem-staged coalesced epilogue.
// CTA tile: 128 rows x 64 cols. 8 warps. A raw in smem (cvt at frag load),
// W pre-blocked+pre-rounded in g_W (no cvt).
// ---------------------------------------------------------------------------
__global__ __launch_bounds__(256) void proj_mma_kernel(
    const float* __restrict__ x1, const float* __restrict__ x2,
    const float* __restrict__ ctx)
{
    extern __shared__ float sm[];
    float* Ab = sm;                  // 2 x (128 x PRA) raw fp32
    float* Wb = sm + 2 * 128 * PRA;  // 2 x VTILE blocked tf32

    const float* A; float* C;
    int which = blockIdx.z;
    if      (which == 0) { A = x1;  C = g_Q;  }
    else if (which == 1) { A = x2;  C = g_Q2; }
    else if (which == 2) { A = ctx; C = g_K;  }
    else                 { A = ctx; C = g_V;  }

    int tid  = threadIdx.x;
    int wid  = tid >> 5, lane = tid & 31, grp = lane >> 2, qd = lane & 3;
    int row0 = blockIdx.x * 128;
    int r0   = wid * 16;
    const float* Wsrc = g_W + (((which * 4 + blockIdx.y) * 8) << 12);

    auto issue = [&](int kb, int buf) {
        float* Ad = Ab + buf * 128 * PRA;
        float* Wd = Wb + buf * VTILE;
        #pragma unroll
        for (int i = 0; i < 8; i++) {            // A: 2048 chunks
            int c = tid + 256 * i;
            int r = c >> 4, w4 = (c & 15) << 2;
            cpa16(&Ad[r * PRA + w4], &A[(size_t)(row0 + r) * QD + kb * 64 + w4]);
        }
        #pragma unroll
        for (int i = 0; i < 4; i++) {            // W: 1024 chunks (blocked layout)
            int o = tid + 256 * i;
            cpa16(&Wd[(o >> 7) * VBLK + ((o >> 5) & 3) * VPN + 4 * (o & 31)],
                  &Wsrc[(kb << 12) + 4 * o]);
        }
    };

    float acc[8][4] = {};

    issue(0, 0);
    asm volatile("cp.async.commit_group;");

    for (int kb = 0; kb < 8; kb++) {
        int cur = kb & 1;
        if (kb + 1 < 8) issue(kb + 1, cur ^ 1);
        asm volatile("cp.async.commit_group;");
        asm volatile("cp.async.wait_group 1;");
        __syncthreads();

        const float* Ac = Ab + cur * 128 * PRA;
        const float* Wc = Wb + cur * VTILE;

        #pragma unroll
        for (int kk = 0; kk < 8; kk++) {
            int kb8 = kk * 8;
            uint32_t a[4];
            a[0] = f2tf(Ac[(r0 + grp) * PRA + kb8 + qd]);
            a[1] = f2tf(Ac[(r0 + grp + 8) * PRA + kb8 + qd]);
            a[2] = f2tf(Ac[(r0 + grp) * PRA + kb8 + qd + 4]);
            a[3] = f2tf(Ac[(r0 + grp + 8) * PRA + kb8 + qd + 4]);
            #pragma unroll
            for (int j = 0; j < 8; j++) {
                float2 bv = *(const float2*)&Wc[kk * VBLK + qd * VPN + 2 * (j * 8 + grp)];
                uint32_t b[2] = { __float_as_uint(bv.x), __float_as_uint(bv.y) };
                mma8(acc[j], a, b);
            }
        }
        __syncthreads();
    }

    int h = blockIdx.y;
    if (which <= 1) {
        // Q / Q2: direct float2 stores (plain row layout)
        #pragma unroll
        for (int j = 0; j < 8; j++) {
            int col = j * 8 + 2 * qd;
            #pragma unroll
            for (int hf = 0; hf < 2; hf++) {
                int R = row0 + r0 + grp + hf * 8;
                int b = R >> 11, ni = R & 2047;
                *(float2*)&C[(((size_t)(b * NH + h)) * ND + ni) * DH + col] =
                    make_float2(f2tf_f(acc[j][2 * hf + 0]), f2tf_f(acc[j][2 * hf + 1]));
            }
        }
    } else {
        // K / V: stage interleaved layout into smem, then coalesced copy-out
        float* St = sm;   // reuse Ab region (all reads done)
        #pragma unroll
        for (int j = 0; j < 8; j++) {
            int col = j * 8 + 2 * qd;
            #pragma unroll
            for (int hf = 0; hf < 2; hf++) {
                int m = r0 + grp + hf * 8;
                float v0 = f2tf_f(acc[j][2 * hf + 0]);
                float v1 = f2tf_f(acc[j][2 * hf + 1]);
                if (which == 2) {
                    St[m * PRA + ilc(col)]     = v0;
                    St[m * PRA + ilc(col + 1)] = v1;
                } else {
                    int base = (m >> 3) * VBLK + (m & 3) * VPN + ((m >> 2) & 1);
                    St[base + 2 * col]       = v0;
                    St[base + 2 * (col + 1)] = v1;
                }
            }
        }
        __syncthreads();
        int b  = row0 >> 11;
        int nb = row0 & 2047;
        float* dst = C + ((size_t)(b * NH + h)) * ND * DH + (size_t)nb * DH;
        if (which == 2) {
            #pragma unroll
            for (int ii = 0; ii < 8; ii++) {
                int o = (tid + 256 * ii) << 2;
                int m = o >> 6, w = o & 63;
                *(float4*)&dst[o] = *(const float4*)&St[m * PRA + w];
            }
        } else {
            #pragma unroll
            for (int ii = 0; ii < 8; ii++) {
                int o = (tid + 256 * ii) << 2;
                int blk = o >> 9, q = (o >> 7) & 3, w = o & 127;
                *(float4*)&dst[o] = *(const float4*)&St[blk * VBLK + q * VPN + w];
            }
        }
    }
}

// ---------------------------------------------------------------------------
// Dual-softmax flash attention: register-resident S, cp.async double-buffered
// K/V tiles, LDS.64 fragment loads. CTA: 64 queries x 64-key tiles, 8 warps.
// Warps 0-3: stream1 (Q,O1); warps 4-7: stream2 (Q2,O2).  [UNCHANGED]
// ---------------------------------------------------------------------------
__global__ __launch_bounds__(256) void attn_mma_kernel()
{
    extern __shared__ float sm[];
    float* KsB = sm;               // 2 x KTILE
    float* VsB = sm + 2 * KTILE;   // 2 x VTILE

    int tid = threadIdx.x;
    int wid = tid >> 5, lane = tid & 31, grp = lane >> 2, qd = lane & 3;
    int half = wid >> 2;
    int wg   = wid & 3;
    int r0   = wg * 16;

    int bh = blockIdx.y, i0 = blockIdx.x * 64;
    const float* Qg = (half ? g_Q2 : g_Q) + ((size_t)bh * ND + i0) * DH;
    const float* Kg = g_K + (size_t)bh * ND * DH;
    const float* Vg = g_V + (size_t)bh * ND * DH;

    uint32_t qf[8][4];
    {
        const float* q0 = Qg + (size_t)(r0 + grp) * DH;
        const float* q1 = Qg + (size_t)(r0 + grp + 8) * DH;
        #pragma unroll
        for (int kk = 0; kk < 8; kk++) {
            qf[kk][0] = __float_as_uint(q0[kk * 8 + qd]     * 0.125f);
            qf[kk][1] = __float_as_uint(q1[kk * 8 + qd]     * 0.125f);
            qf[kk][2] = __float_as_uint(q0[kk * 8 + qd + 4] * 0.125f);
            qf[kk][3] = __float_as_uint(q1[kk * 8 + qd + 4] * 0.125f);
        }
    }

    float O[8][4] = {};
    float m_lo = -1e30f, m_hi = -1e30f, l_lo = 0.f, l_hi = 0.f;

    auto issue_tile = [&](int kt, int buf) {
        const float* Kt = Kg + (size_t)kt * 64 * DH;
        const float* Vt = Vg + (size_t)kt * 64 * DH;
        float* Kd = KsB + buf * KTILE;
        float* Vd = VsB + buf * VTILE;
        #pragma unroll
        for (int i = 0; i < 4; i++) {
            int c = tid + 256 * i;
            int n = c >> 4, w = (c & 15) << 2;
            cpa16(&Kd[n * KP + w], &Kt[n * 64 + w]);
            int o = c << 2;
            int blk = o >> 9, q = (o >> 7) & 3, wo = o & 127;
            cpa16(&Vd[blk * VBLK + q * VPN + wo], &Vt[o]);
        }
    };

    issue_tile(0, 0);
    asm volatile("cp.async.commit_group;");

    for (int kt = 0; kt < 32; kt++) {
        int cur = kt & 1;
        if (kt + 1 < 32) issue_tile(kt + 1, cur ^ 1);
        asm volatile("cp.async.commit_group;");
        asm volatile("cp.async.wait_group 1;");
        __syncthreads();

        const float* Ksb = KsB + cur * KTILE;
        const float* Vsb = VsB + cur * VTILE;

        float sacc[8][4] = {};
        #pragma unroll
        for (int kk = 0; kk < 8; kk++) {
            int kb = kk * 8;
            #pragma unroll
            for (int j = 0; j < 8; j++) {
                float2 bv = *(const float2*)&Ksb[(j * 8 + grp) * KP + kb + 2 * qd];
                uint32_t b[2] = { __float_as_uint(bv.x), __float_as_uint(bv.y) };
                mma8(sacc[j], qf[kk], b);
            }
        }

        {
            float mx_lo = -1e30f, mx_hi = -1e30f;
            #pragma unroll
            for (int j = 0; j < 8; j++) {
                mx_lo = fmaxf(mx_lo, fmaxf(sacc[j][0], sacc[j][1]));
                mx_hi = fmaxf(mx_hi, fmaxf(sacc[j][2], sacc[j][3]));
            }
            mx_lo = fmaxf(mx_lo, __shfl_xor_sync(0xffffffffu, mx_lo, 1));
            mx_lo = fmaxf(mx_lo, __shfl_xor_sync(0xffffffffu, mx_lo, 2));
            mx_hi = fmaxf(mx_hi, __shfl_xor_sync(0xffffffffu, mx_hi, 1));
            mx_hi = fmaxf(mx_hi, __shfl_xor_sync(0xffffffffu, mx_hi, 2));
            float mn_lo = fmaxf(m_lo, mx_lo), mn_hi = fmaxf(m_hi, mx_hi);
            float al_lo = __expf(m_lo - mn_lo), al_hi = __expf(m_hi - mn_hi);
            m_lo = mn_lo; m_hi = mn_hi;
            float s_lo = 0.f, s_hi = 0.f;
            #pragma unroll
            for (int j = 0; j < 8; j++) {
                sacc[j][0] = __expf(sacc[j][0] - mn_lo); s_lo += sacc[j][0];
                sacc[j][1] = __expf(sacc[j][1] - mn_lo); s_lo += sacc[j][1];
                sacc[j][2] = __expf(sacc[j][2] - mn_hi); s_hi += sacc[j][2];
                sacc[j][3] = __expf(sacc[j][3] - mn_hi); s_hi += sacc[j][3];
            }
            s_lo += __shfl_xor_sync(0xffffffffu, s_lo, 1);
            s_lo += __shfl_xor_sync(0xffffffffu, s_lo, 2);
            s_hi += __shfl_xor_sync(0xffffffffu, s_hi, 1);
            s_hi += __shfl_xor_sync(0xffffffffu, s_hi, 2);
            l_lo = l_lo * al_lo + s_lo;
            l_hi = l_hi * al_hi + s_hi;
            #pragma unroll
            for (int j = 0; j < 8; j++) {
                O[j][0] *= al_lo; O[j][1] *= al_lo;
                O[j][2] *= al_hi; O[j][3] *= al_hi;
            }
        }

        {
            int src  = qd >> 1;
            int src2 = src + 2;
            bool odd = qd & 1;
            #pragma unroll
            for (int kk = 0; kk < 8; kk++) {
                float x0 = __shfl_sync(0xffffffffu, sacc[kk][0], src, 4);
                float x1 = __shfl_sync(0xffffffffu, sacc[kk][1], src, 4);
                float x2 = __shfl_sync(0xffffffffu, sacc[kk][2], src, 4);
                float x3 = __shfl_sync(0xffffffffu, sacc[kk][3], src, 4);
                float y0 = __shfl_sync(0xffffffffu, sacc[kk][0], src2, 4);
                float y1 = __shfl_sync(0xffffffffu, sacc[kk][1], src2, 4);
                float y2 = __shfl_sync(0xffffffffu, sacc[kk][2], src2, 4);
                float y3 = __shfl_sync(0xffffffffu, sacc[kk][3], src2, 4);
                uint32_t a[4];
                a[0] = f2tf(odd ? x1 : x0);
                a[1] = f2tf(odd ? x3 : x2);
                a[2] = f2tf(odd ? y1 : y0);
                a[3] = f2tf(odd ? y3 : y2);
                #pragma unroll
                for (int j = 0; j < 8; j++) {
                    float2 v = *(const float2*)&Vsb[kk * VBLK + qd * VPN + 2 * (j * 8 + grp)];
                    uint32_t b[2] = { __float_as_uint(v.x), __float_as_uint(v.y) };
                    mma8(O[j], a, b);
                }
            }
        }
        __syncthreads();
    }

    if (half == 0) {
        float s_lo = 0.3f / l_lo, s_hi = 0.3f / l_hi;
        #pragma unroll
        for (int j = 0; j < 8; j++) {
            int col = j * 8 + 2 * qd;
            *(float2*)&KsB[(r0 + grp) * KP + col] =
                make_float2(O[j][0] * s_lo, O[j][1] * s_lo);
            *(float2*)&KsB[(r0 + grp + 8) * KP + col] =
                make_float2(O[j][2] * s_hi, O[j][3] * s_hi);
        }
    }
    __syncthreads();
    if (half == 1) {
        float s_lo = 0.7f / l_lo, s_hi = 0.7f / l_hi;
        int b = bh >> 2, h = bh & 3;
        float* outp = g_Ao + ((size_t)b * ND + i0) * INNER + h * DH;
        #pragma unroll
        for (int j = 0; j < 8; j++) {
            int col = j * 8 + 2 * qd;
            float2 p = *(float2*)&KsB[(r0 + grp) * KP + col];
            *(float2*)&outp[(size_t)(r0 + grp) * INNER + col] =
                make_float2(p.x + O[j][0] * s_lo, p.y + O[j][1] * s_lo);
            p = *(float2*)&KsB[(r0 + grp + 8) * KP + col];
            *(float2*)&outp[(size_t)(r0 + grp + 8) * INNER + col] =
                make_float2(p.x + O[j][2] * s_hi, p.y + O[j][3] * s_hi);
        }
    }
}

// ---------------------------------------------------------------------------
// Output projection (tf32 MMA, cp.async double-buffered):
// out = Ao[8192,256] @ Wo[256,512] + bo.  Wo pre-blocked in g_Wo.
// ---------------------------------------------------------------------------
__global__ __launch_bounds__(256) void outproj_mma_kernel(
    const float* __restrict__ bo, float* __restrict__ out)
{
    extern __shared__ float sm[];
    float* Ab = sm;                  // 2 x (128 x PRA) raw fp32
    float* Wb = sm + 2 * 128 * PRA;  // 2 x VTILE blocked tf32

    int tid  = threadIdx.x;
    int wid  = tid >> 5, lane = tid & 31, grp = lane >> 2, qd = lane & 3;
    int row0 = blockIdx.x * 128;
    int col0 = blockIdx.y * 64;
    int r0   = wid * 16;
    const float* Wsrc = g_Wo + ((blockIdx.y * 4) << 12);

    auto issue = [&](int kb, int buf) {
        float* Ad = Ab + buf * 128 * PRA;
        float* Wd = Wb + buf * VTILE;
        #pragma unroll
        for (int i = 0; i < 8; i++) {
            int c = tid + 256 * i;
            int r = c >> 4, w4 = (c & 15) << 2;
            cpa16(&Ad[r * PRA + w4], &g_Ao[(size_t)(row0 + r) * INNER + kb * 64 + w4]);
        }
        #pragma unroll
        for (int i = 0; i < 4; i++) {
            int o = tid + 256 * i;
            cpa16(&Wd[(o >> 7) * VBLK + ((o >> 5) & 3) * VPN + 4 * (o & 31)],
                  &Wsrc[(kb << 12) + 4 * o]);
        }
    };

    float acc[8][4] = {};

    issue(0, 0);
    asm volatile("cp.async.commit_group;");

    for (int kb = 0; kb < 4; kb++) {
        int cur = kb & 1;
        if (kb + 1 < 4) issue(kb + 1, cur ^ 1);
        asm volatile("cp.async.commit_group;");
        asm volatile("cp.async.wait_group 1;");
        __syncthreads();

        const float* Ac = Ab + cur * 128 * PRA;
        const float* Wc = Wb + cur * VTILE;

        #pragma unroll
        for (int kk = 0; kk < 8; kk++) {
            int kb8 = kk * 8;
            uint32_t a[4];
            a[0] = f2tf(Ac[(r0 + grp) * PRA + kb8 + qd]);
            a[1] = f2tf(Ac[(r0 + grp + 8) * PRA + kb8 + qd]);
            a[2] = f2tf(Ac[(r0 + grp) * PRA + kb8 + qd + 4]);
            a[3] = f2tf(Ac[(r0 + grp + 8) * PRA + kb8 + qd + 4]);
            #pragma unroll
            for (int j = 0; j < 8; j++) {
                float2 bv = *(const float2*)&Wc[kk * VBLK + qd * VPN + 2 * (j * 8 + grp)];
                uint32_t b[2] = { __float_as_uint(bv.x), __float_as_uint(bv.y) };
                mma8(acc[j], a, b);
            }
        }
        __syncthreads();
    }

    #pragma unroll
    for (int j = 0; j < 8; j++) {
        int col = j * 8 + 2 * qd;
        float b0 = bo[col0 + col], b1 = bo[col0 + col + 1];
        int R = row0 + r0 + grp;
        *(float2*)&out[(size_t)R * QD + col0 + col] =
            make_float2(acc[j][0] + b0, acc[j][1] + b1);
        R += 8;
        *(float2*)&out[(size_t)R * QD + col0 + col] =
            make_float2(acc[j][2] + b0, acc[j][3] + b1);
    }
}

// ---------------------------------------------------------------------------
extern "C" void kernel_launch(void* const* d_in, const int* in_sizes, int n_in,
                              void* d_out, int out_size)
{
    const float* x1  = (const float*)d_in[0];
    const float* x2  = (const float*)d_in[1];
    const float* ctx = (const float*)d_in[2];
    const float* Wq  = (const float*)d_in[3];
    const float* Wq2 = (const float*)d_in[4];
    const float* Wk  = (const float*)d_in[5];
    const float* Wv  = (const float*)d_in[6];
    const float* Wo  = (const float*)d_in[7];
    const float* bo  = (const float*)d_in[8];
    float* out = (float*)d_out;

    const int gemm_smem = (2 * 128 * PRA + 2 * VTILE) * sizeof(float); // ~104.4 KB
    const int attn_smem = 2 * (KTILE + VTILE) * sizeof(float);         // 71.7 KB

    // Unconditional (no static guards); idempotent host-side calls.
    cudaFuncSetAttribute(proj_mma_kernel,
        cudaFuncAttributeMaxDynamicSharedMemorySize, gemm_smem);
    cudaFuncSetAttribute(attn_mma_kernel,
        cudaFuncAttributeMaxDynamicSharedMemorySize, attn_smem);
    cudaFuncSetAttribute(outproj_mma_kernel,
        cudaFuncAttributeMaxDynamicSharedMemorySize, gemm_smem);

    // 0) weight prep: tf32-round + block layouts (4 proj weights + Wo)
    prep_w_kernel<<<(4 * QD * INNER + INNER * QD) / 256, 256>>>(Wq, Wq2, Wk, Wv, Wo);

    // 1) projections: Q, Q2, K, V (cp.async pipelined tf32 MMA)
    proj_mma_kernel<<<dim3(64, 4, 4), 256, gemm_smem>>>(x1, x2, ctx);

    // 2) dual-softmax flash attention (cp.async double-buffered, tf32 MMA)
    attn_mma_kernel<<<dim3(32, 16), 256, attn_smem>>>();

    // 3) output projection + bias (cp.async pipelined tf32 MMA)
    outproj_mma_kernel<<<dim3(64, 8), 256, gemm_smem>>>(bo, out);
}